// round 1
// baseline (speedup 1.0000x reference)
#include <cuda_runtime.h>
#include <math.h>

// Problem constants
#define Bc 2
#define Sc 2048
#define Hc 4096
#define NHc 16
#define HDc 256
#define RDc 64
#define F3H 12288   // 3*H

// ---------------- scratch (no allocation allowed) ----------------
__device__ float g_qkv[(size_t)4096 * 12288];   // [B*S][3H]
__device__ float g_Q[(size_t)2 * 16 * 2048 * 256]; // [B][NH][S][HD]
__device__ float g_K[(size_t)2 * 16 * 2048 * 256];
__device__ float g_V[(size_t)2 * 16 * 2048 * 256];
__device__ float g_attn[(size_t)4096 * 4096];   // [B*S][H]

// ---------------- SGEMM: C = A[MxK] * B[KxN], row-major, fp32 ----------------
#define GBM 128
#define GBN 128
#define GBK 16

__global__ __launch_bounds__(256) void sgemm_kernel(
    const float* __restrict__ A, const float* __restrict__ B,
    float* __restrict__ C, int M, int N, int K)
{
    __shared__ float As[GBK][GBM];
    __shared__ float Bs[GBK][GBN];

    const int tid = threadIdx.x;
    const int tx = tid & 15;
    const int ty = tid >> 4;
    const int rowBase = blockIdx.y * GBM;
    const int colBase = blockIdx.x * GBN;

    float acc[8][8];
    #pragma unroll
    for (int i = 0; i < 8; i++)
        #pragma unroll
        for (int j = 0; j < 8; j++) acc[i][j] = 0.f;

    for (int k0 = 0; k0 < K; k0 += GBK) {
        // load A tile (128x16) transposed into As
        #pragma unroll
        for (int i = 0; i < 2; i++) {
            int v = tid + i * 256;
            int ar = v >> 2;
            int ac = (v & 3) * 4;
            float4 a = *(const float4*)&A[(size_t)(rowBase + ar) * K + k0 + ac];
            As[ac + 0][ar] = a.x;
            As[ac + 1][ar] = a.y;
            As[ac + 2][ar] = a.z;
            As[ac + 3][ar] = a.w;
        }
        // load B tile (16x128)
        #pragma unroll
        for (int i = 0; i < 2; i++) {
            int v = tid + i * 256;
            int br = v >> 5;
            int bc = (v & 31) * 4;
            *(float4*)&Bs[br][bc] =
                *(const float4*)&B[(size_t)(k0 + br) * N + colBase + bc];
        }
        __syncthreads();

        #pragma unroll
        for (int kk = 0; kk < GBK; kk++) {
            float4 a0 = *(float4*)&As[kk][ty * 8];
            float4 a1 = *(float4*)&As[kk][ty * 8 + 4];
            float4 b0 = *(float4*)&Bs[kk][tx * 8];
            float4 b1 = *(float4*)&Bs[kk][tx * 8 + 4];
            float ar[8] = {a0.x, a0.y, a0.z, a0.w, a1.x, a1.y, a1.z, a1.w};
            float br[8] = {b0.x, b0.y, b0.z, b0.w, b1.x, b1.y, b1.z, b1.w};
            #pragma unroll
            for (int i = 0; i < 8; i++)
                #pragma unroll
                for (int j = 0; j < 8; j++)
                    acc[i][j] += ar[i] * br[j];
        }
        __syncthreads();
    }

    #pragma unroll
    for (int i = 0; i < 8; i++) {
        size_t r = (size_t)(rowBase + ty * 8 + i);
        float4* cp = (float4*)&C[r * N + colBase + tx * 8];
        cp[0] = make_float4(acc[i][0], acc[i][1], acc[i][2], acc[i][3]);
        cp[1] = make_float4(acc[i][4], acc[i][5], acc[i][6], acc[i][7]);
    }
}

// ---------------- RoPE + split/scatter ----------------
// qkv columns: [0:4096) = q, [4096:8192) = v, [8192:12288) = k  (reference split order!)
__global__ void rope_scatter_kernel(
    const float* __restrict__ qkv, const int* __restrict__ pos_ids,
    float* __restrict__ Q, float* __restrict__ K, float* __restrict__ V)
{
    size_t p = (size_t)blockIdx.x * blockDim.x + threadIdx.x; // pair id
    int row = (int)(p / 6144);      // b*S + s
    int col = ((int)(p % 6144)) * 2;
    int b = row >> 11;
    int s = row & 2047;
    int sect = col >> 12;           // /4096
    int f = col - (sect << 12);
    int hh = f >> 8;
    int d = f & 255;

    float2 x = *(const float2*)&qkv[(size_t)row * F3H + col];
    size_t dst = ((size_t)((b * NHc + hh) * Sc + s)) * HDc + d;

    if (sect == 1) {
        *(float2*)&V[dst] = x;
    } else {
        float2 y = x;
        if (d < RDc) {
            // inv_freq = 10000^(-d/64), d even
            float inv = expf(-(float)d * (9.210340371976184f / 64.f));
            float fr = (float)pos_ids[row] * inv;
            float c, sn;
            sincosf(fr, &sn, &c);
            y.x = x.x * c - x.y * sn;
            y.y = x.y * c + x.x * sn;
        }
        if (sect == 0) *(float2*)&Q[dst] = y;
        else           *(float2*)&K[dst] = y;
    }
}

// ---------------- flash attention, fp32, causal ----------------
#define ATT_BM 64
#define ATT_BN 64
#define QP 260   // padded row length for Qs/Ks (bank-conflict pad)
#define PP 68    // padded row length for Ps

#define ATTN_SMEM_FLOATS (64 * QP + 64 * QP + 64 * HDc + 64 * PP + 3 * 64)

__global__ __launch_bounds__(256) void attn_kernel(
    const float* __restrict__ Q, const float* __restrict__ K,
    const float* __restrict__ V, float* __restrict__ O)
{
    extern __shared__ float sm[];
    float* Qs  = sm;                  // [64][QP]
    float* Ks  = Qs + 64 * QP;        // [64][QP]
    float* Vs  = Ks + 64 * QP;        // [64][HD]
    float* Ps  = Vs + 64 * HDc;       // [64][PP]
    float* m_s = Ps + 64 * PP;        // [64]
    float* l_s = m_s + 64;            // [64]
    float* al_s = l_s + 64;           // [64]

    const int tid = threadIdx.x;
    const int qt = blockIdx.x, hh = blockIdx.y, b = blockIdx.z;
    const int q0 = qt * ATT_BM;

    const float* Qg = Q + ((size_t)(b * NHc + hh) * Sc) * HDc;
    const float* Kg = K + ((size_t)(b * NHc + hh) * Sc) * HDc;
    const float* Vg = V + ((size_t)(b * NHc + hh) * Sc) * HDc;

    // load Q tile
    for (int v = tid; v < ATT_BM * HDc / 4; v += 256) {
        int r = v >> 6;
        int c4 = (v & 63) << 2;
        *(float4*)&Qs[r * QP + c4] =
            *(const float4*)&Qg[(size_t)(q0 + r) * HDc + c4];
    }
    if (tid < 64) { m_s[tid] = -1e30f; l_s[tid] = 0.f; }

    float o[8][8];
    #pragma unroll
    for (int i = 0; i < 8; i++)
        #pragma unroll
        for (int j = 0; j < 8; j++) o[i][j] = 0.f;

    const int py = tid >> 5, px = tid & 31;   // PV map: 8 rows x 8 cols per thread
    const int sy = tid >> 4, sx = tid & 15;   // score map: 4x4 per thread

    for (int kt = 0; kt <= qt; ++kt) {
        __syncthreads();   // Q tile ready (1st iter) / previous PV done

        const int k0 = kt * ATT_BN;
        for (int v = tid; v < ATT_BN * HDc / 4; v += 256) {
            int r = v >> 6;
            int c4 = (v & 63) << 2;
            *(float4*)&Ks[r * QP + c4] =
                *(const float4*)&Kg[(size_t)(k0 + r) * HDc + c4];
            *(float4*)&Vs[r * HDc + c4] =
                *(const float4*)&Vg[(size_t)(k0 + r) * HDc + c4];
        }
        __syncthreads();

        // scores S = Q K^T (4x4 per thread)
        float sa[4][4];
        #pragma unroll
        for (int i = 0; i < 4; i++)
            #pragma unroll
            for (int j = 0; j < 4; j++) sa[i][j] = 0.f;

        #pragma unroll 4
        for (int k = 0; k < HDc; k += 4) {
            float4 a[4], bb[4];
            #pragma unroll
            for (int i = 0; i < 4; i++)
                a[i] = *(float4*)&Qs[(sy * 4 + i) * QP + k];
            #pragma unroll
            for (int j = 0; j < 4; j++)
                bb[j] = *(float4*)&Ks[(sx * 4 + j) * QP + k];
            #pragma unroll
            for (int i = 0; i < 4; i++)
                #pragma unroll
                for (int j = 0; j < 4; j++)
                    sa[i][j] += a[i].x * bb[j].x + a[i].y * bb[j].y +
                                a[i].z * bb[j].z + a[i].w * bb[j].w;
        }

        // scale + causal mask + stash
        #pragma unroll
        for (int i = 0; i < 4; i++) {
            int qg = q0 + sy * 4 + i;
            #pragma unroll
            for (int j = 0; j < 4; j++) {
                int kg = k0 + sx * 4 + j;
                float vsc = sa[i][j] * 0.0625f;   // HD^-0.5 = 1/16
                if (kg > qg) vsc = -1e30f;
                Ps[(sy * 4 + i) * PP + sx * 4 + j] = vsc;
            }
        }
        __syncthreads();

        // online softmax (one thread per row)
        if (tid < 64) {
            int r = tid;
            float mold = m_s[r];
            float mt = mold;
            for (int c = 0; c < 64; c++) mt = fmaxf(mt, Ps[r * PP + c]);
            float alpha = __expf(mold - mt);
            float sum = 0.f;
            for (int c = 0; c < 64; c++) {
                float pv = __expf(Ps[r * PP + c] - mt);
                Ps[r * PP + c] = pv;
                sum += pv;
            }
            m_s[r] = mt;
            l_s[r] = l_s[r] * alpha + sum;
            al_s[r] = alpha;
        }
        __syncthreads();

        // O = O*alpha + P V  (8x8 per thread)
        #pragma unroll
        for (int i = 0; i < 8; i++) {
            float al = al_s[py * 8 + i];
            #pragma unroll
            for (int j = 0; j < 8; j++) o[i][j] *= al;
        }
        #pragma unroll 2
        for (int kk = 0; kk < ATT_BN; kk += 4) {
            float4 a[8];
            #pragma unroll
            for (int i = 0; i < 8; i++)
                a[i] = *(float4*)&Ps[(py * 8 + i) * PP + kk];
            #pragma unroll
            for (int k2 = 0; k2 < 4; k2++) {
                float4 b0 = *(float4*)&Vs[(kk + k2) * HDc + px * 8];
                float4 b1 = *(float4*)&Vs[(kk + k2) * HDc + px * 8 + 4];
                #pragma unroll
                for (int i = 0; i < 8; i++) {
                    float av = (k2 == 0) ? a[i].x : (k2 == 1) ? a[i].y
                             : (k2 == 2) ? a[i].z : a[i].w;
                    o[i][0] += av * b0.x; o[i][1] += av * b0.y;
                    o[i][2] += av * b0.z; o[i][3] += av * b0.w;
                    o[i][4] += av * b1.x; o[i][5] += av * b1.y;
                    o[i][6] += av * b1.z; o[i][7] += av * b1.w;
                }
            }
        }
    }

    // epilogue: normalize + write [B][S][H] (h*HD + d)
    #pragma unroll
    for (int i = 0; i < 8; i++) {
        int r = py * 8 + i;
        float inv = 1.f / l_s[r];
        size_t base = ((size_t)(b * Sc + q0 + r)) * Hc + hh * HDc + px * 8;
        *(float4*)&O[base] =
            make_float4(o[i][0] * inv, o[i][1] * inv, o[i][2] * inv, o[i][3] * inv);
        *(float4*)&O[base + 4] =
            make_float4(o[i][4] * inv, o[i][5] * inv, o[i][6] * inv, o[i][7] * inv);
    }
}

// ---------------- launch ----------------
extern "C" void kernel_launch(void* const* d_in, const int* in_sizes, int n_in,
                              void* d_out, int out_size)
{
    const float* hidden = (const float*)d_in[0];
    const int*   pos    = (const int*)d_in[1];
    const float* w_qkv  = (const float*)d_in[2];
    const float* w_out  = (const float*)d_in[3];
    float* out = (float*)d_out;

    float *qkv, *Q, *K, *V, *attn;
    cudaGetSymbolAddress((void**)&qkv,  g_qkv);
    cudaGetSymbolAddress((void**)&Q,    g_Q);
    cudaGetSymbolAddress((void**)&K,    g_K);
    cudaGetSymbolAddress((void**)&V,    g_V);
    cudaGetSymbolAddress((void**)&attn, g_attn);

    // 1) qkv = hidden @ w_qkv   [4096,4096] x [4096,12288]
    sgemm_kernel<<<dim3(F3H / GBN, 4096 / GBM), 256>>>(
        hidden, w_qkv, qkv, 4096, F3H, 4096);

    // 2) RoPE + split into Q/K/V [B][NH][S][HD]
    {
        size_t pairs = (size_t)4096 * 6144;
        rope_scatter_kernel<<<(unsigned)(pairs / 256), 256>>>(qkv, pos, Q, K, V);
    }

    // 3) causal flash attention -> attn [B*S][H]
    {
        size_t smem = (size_t)ATTN_SMEM_FLOATS * sizeof(float);
        cudaFuncSetAttribute(attn_kernel,
                             cudaFuncAttributeMaxDynamicSharedMemorySize,
                             (int)smem);
        attn_kernel<<<dim3(Sc / ATT_BM, NHc, Bc), 256, smem>>>(Q, K, V, attn);
    }

    // 4) out = attn @ w_out   [4096,4096] x [4096,4096]
    sgemm_kernel<<<dim3(4096 / GBN, 4096 / GBM), 256>>>(
        attn, w_out, out, 4096, 4096, 4096);
}

// round 2
// speedup vs baseline: 1.9142x; 1.9142x over previous
#include <cuda_runtime.h>
#include <math.h>

// Problem constants
#define Bc 2
#define Sc 2048
#define Hc 4096
#define NHc 16
#define HDc 256
#define RDc 64
#define F3H 12288   // 3*H

// ---------------- scratch (no allocation allowed) ----------------
__device__ float g_qkv[(size_t)4096 * 12288];   // [B*S][3H]
__device__ float g_Q[(size_t)2 * 16 * 2048 * 256]; // [B][NH][S][HD]
__device__ float g_K[(size_t)2 * 16 * 2048 * 256];
__device__ float g_V[(size_t)2 * 16 * 2048 * 256];
__device__ float g_attn[(size_t)4096 * 4096];   // [B*S][H]

// ---------------- tf32 tensor-core GEMM ----------------
// C[MxN] = A[MxK] * B[KxN], row-major fp32 in/out, tf32 mma accumulate fp32.
#define TBM 128
#define TBN 128
#define TBK 32
#define ASTRIDE 137   // As[k][m], odd stride -> conflict-free scalar STS
#define BSTRIDE 132   // Bs[k][n], float4-aligned stride

__device__ __forceinline__ unsigned f2tf32(float x) {
    unsigned u;
    asm("cvt.rna.tf32.f32 %0, %1;" : "=r"(u) : "f"(x));
    return u;
}

__device__ __forceinline__ void mma_tf32(float* d, const unsigned* a, const unsigned* b) {
    asm volatile(
        "mma.sync.aligned.m16n8k8.row.col.f32.tf32.tf32.f32 "
        "{%0,%1,%2,%3}, {%4,%5,%6,%7}, {%8,%9}, {%0,%1,%2,%3};\n"
        : "+f"(d[0]), "+f"(d[1]), "+f"(d[2]), "+f"(d[3])
        : "r"(a[0]), "r"(a[1]), "r"(a[2]), "r"(a[3]), "r"(b[0]), "r"(b[1]));
}

__global__ __launch_bounds__(256) void tf32_gemm_kernel(
    const float* __restrict__ A, const float* __restrict__ B,
    float* __restrict__ C, int M, int N, int K)
{
    __shared__ unsigned As[TBK * ASTRIDE];
    __shared__ unsigned Bs[TBK * BSTRIDE];

    const int tid  = threadIdx.x;
    const int lane = tid & 31;
    const int wid  = tid >> 5;
    const int wm   = (wid & 1) * 64;   // warp row offset
    const int wn   = (wid >> 1) * 32;  // warp col offset
    const int lr   = lane >> 2;        // 0..7
    const int lc   = lane & 3;         // 0..3
    const int rowBase = blockIdx.y * TBM;
    const int colBase = blockIdx.x * TBN;

    float acc[4][4][4];
    #pragma unroll
    for (int mt = 0; mt < 4; mt++)
        #pragma unroll
        for (int nt = 0; nt < 4; nt++)
            #pragma unroll
            for (int i = 0; i < 4; i++) acc[mt][nt][i] = 0.f;

    for (int k0 = 0; k0 < K; k0 += TBK) {
        // stage A tile (128x32) into As[k][m], converting to tf32
        #pragma unroll
        for (int i = 0; i < 4; i++) {
            int r  = (tid >> 3) + i * 32;
            int c4 = (tid & 7) * 4;
            float4 a = *(const float4*)&A[(size_t)(rowBase + r) * K + k0 + c4];
            As[(c4 + 0) * ASTRIDE + r] = f2tf32(a.x);
            As[(c4 + 1) * ASTRIDE + r] = f2tf32(a.y);
            As[(c4 + 2) * ASTRIDE + r] = f2tf32(a.z);
            As[(c4 + 3) * ASTRIDE + r] = f2tf32(a.w);
        }
        // stage B tile (32x128) into Bs[k][n], converting to tf32
        #pragma unroll
        for (int i = 0; i < 4; i++) {
            int r  = (tid >> 5) + i * 8;
            int c4 = (tid & 31) * 4;
            float4 b = *(const float4*)&B[(size_t)(k0 + r) * N + colBase + c4];
            uint4 ub = make_uint4(f2tf32(b.x), f2tf32(b.y), f2tf32(b.z), f2tf32(b.w));
            *(uint4*)&Bs[r * BSTRIDE + c4] = ub;
        }
        __syncthreads();

        #pragma unroll
        for (int kk = 0; kk < TBK; kk += 8) {
            unsigned af[4][4], bf[4][2];
            #pragma unroll
            for (int mt = 0; mt < 4; mt++) {
                int m0 = wm + mt * 16;
                af[mt][0] = As[(kk + lc) * ASTRIDE + m0 + lr];
                af[mt][1] = As[(kk + lc) * ASTRIDE + m0 + lr + 8];
                af[mt][2] = As[(kk + 4 + lc) * ASTRIDE + m0 + lr];
                af[mt][3] = As[(kk + 4 + lc) * ASTRIDE + m0 + lr + 8];
            }
            #pragma unroll
            for (int nt = 0; nt < 4; nt++) {
                int n0 = wn + nt * 8;
                bf[nt][0] = Bs[(kk + lc) * BSTRIDE + n0 + lr];
                bf[nt][1] = Bs[(kk + 4 + lc) * BSTRIDE + n0 + lr];
            }
            #pragma unroll
            for (int mt = 0; mt < 4; mt++)
                #pragma unroll
                for (int nt = 0; nt < 4; nt++)
                    mma_tf32(acc[mt][nt], af[mt], bf[nt]);
        }
        __syncthreads();
    }

    // epilogue
    #pragma unroll
    for (int mt = 0; mt < 4; mt++) {
        #pragma unroll
        for (int nt = 0; nt < 4; nt++) {
            int gr = rowBase + wm + mt * 16 + lr;
            int gc = colBase + wn + nt * 8 + 2 * lc;
            *(float2*)&C[(size_t)gr * N + gc] =
                make_float2(acc[mt][nt][0], acc[mt][nt][1]);
            *(float2*)&C[(size_t)(gr + 8) * N + gc] =
                make_float2(acc[mt][nt][2], acc[mt][nt][3]);
        }
    }
}

// ---------------- RoPE + split/scatter ----------------
// qkv columns: [0:4096) = q, [4096:8192) = v, [8192:12288) = k  (reference split order!)
__global__ void rope_scatter_kernel(
    const float* __restrict__ qkv, const int* __restrict__ pos_ids,
    float* __restrict__ Q, float* __restrict__ K, float* __restrict__ V)
{
    size_t p = (size_t)blockIdx.x * blockDim.x + threadIdx.x; // pair id
    int row = (int)(p / 6144);      // b*S + s
    int col = ((int)(p % 6144)) * 2;
    int b = row >> 11;
    int s = row & 2047;
    int sect = col >> 12;           // /4096
    int f = col - (sect << 12);
    int hh = f >> 8;
    int d = f & 255;

    float2 x = *(const float2*)&qkv[(size_t)row * F3H + col];
    size_t dst = ((size_t)((b * NHc + hh) * Sc + s)) * HDc + d;

    if (sect == 1) {
        *(float2*)&V[dst] = x;
    } else {
        float2 y = x;
        if (d < RDc) {
            float inv = expf(-(float)d * (9.210340371976184f / 64.f));
            float fr = (float)pos_ids[row] * inv;
            float c, sn;
            sincosf(fr, &sn, &c);
            y.x = x.x * c - x.y * sn;
            y.y = x.y * c + x.x * sn;
        }
        if (sect == 0) *(float2*)&Q[dst] = y;
        else           *(float2*)&K[dst] = y;
    }
}

// ---------------- flash attention, fp32, causal ----------------
#define ATT_BM 64
#define ATT_BN 64
#define QP 260   // padded row length for Qs/Ks
#define PP 68    // padded row length for Ps

#define ATTN_SMEM_FLOATS (64 * QP + 64 * QP + 64 * HDc + 64 * PP + 3 * 64)

__global__ __launch_bounds__(256) void attn_kernel(
    const float* __restrict__ Q, const float* __restrict__ K,
    const float* __restrict__ V, float* __restrict__ O)
{
    extern __shared__ float sm[];
    float* Qs  = sm;                  // [64][QP]
    float* Ks  = Qs + 64 * QP;        // [64][QP]
    float* Vs  = Ks + 64 * QP;        // [64][HD]
    float* Ps  = Vs + 64 * HDc;       // [64][PP]
    float* m_s = Ps + 64 * PP;        // [64]
    float* l_s = m_s + 64;            // [64]
    float* al_s = l_s + 64;           // [64]

    const int tid = threadIdx.x;
    const int qt = blockIdx.x, hh = blockIdx.y, b = blockIdx.z;
    const int q0 = qt * ATT_BM;

    const float* Qg = Q + ((size_t)(b * NHc + hh) * Sc) * HDc;
    const float* Kg = K + ((size_t)(b * NHc + hh) * Sc) * HDc;
    const float* Vg = V + ((size_t)(b * NHc + hh) * Sc) * HDc;

    for (int v = tid; v < ATT_BM * HDc / 4; v += 256) {
        int r = v >> 6;
        int c4 = (v & 63) << 2;
        *(float4*)&Qs[r * QP + c4] =
            *(const float4*)&Qg[(size_t)(q0 + r) * HDc + c4];
    }
    if (tid < 64) { m_s[tid] = -1e30f; l_s[tid] = 0.f; }

    float o[8][8];
    #pragma unroll
    for (int i = 0; i < 8; i++)
        #pragma unroll
        for (int j = 0; j < 8; j++) o[i][j] = 0.f;

    const int py = tid >> 5, px = tid & 31;
    const int sy = tid >> 4, sx = tid & 15;

    for (int kt = 0; kt <= qt; ++kt) {
        __syncthreads();

        const int k0 = kt * ATT_BN;
        for (int v = tid; v < ATT_BN * HDc / 4; v += 256) {
            int r = v >> 6;
            int c4 = (v & 63) << 2;
            *(float4*)&Ks[r * QP + c4] =
                *(const float4*)&Kg[(size_t)(k0 + r) * HDc + c4];
            *(float4*)&Vs[r * HDc + c4] =
                *(const float4*)&Vg[(size_t)(k0 + r) * HDc + c4];
        }
        __syncthreads();

        float sa[4][4];
        #pragma unroll
        for (int i = 0; i < 4; i++)
            #pragma unroll
            for (int j = 0; j < 4; j++) sa[i][j] = 0.f;

        #pragma unroll 4
        for (int k = 0; k < HDc; k += 4) {
            float4 a[4], bb[4];
            #pragma unroll
            for (int i = 0; i < 4; i++)
                a[i] = *(float4*)&Qs[(sy * 4 + i) * QP + k];
            #pragma unroll
            for (int j = 0; j < 4; j++)
                bb[j] = *(float4*)&Ks[(sx * 4 + j) * QP + k];
            #pragma unroll
            for (int i = 0; i < 4; i++)
                #pragma unroll
                for (int j = 0; j < 4; j++)
                    sa[i][j] += a[i].x * bb[j].x + a[i].y * bb[j].y +
                                a[i].z * bb[j].z + a[i].w * bb[j].w;
        }

        #pragma unroll
        for (int i = 0; i < 4; i++) {
            int qg = q0 + sy * 4 + i;
            #pragma unroll
            for (int j = 0; j < 4; j++) {
                int kg = k0 + sx * 4 + j;
                float vsc = sa[i][j] * 0.0625f;
                if (kg > qg) vsc = -1e30f;
                Ps[(sy * 4 + i) * PP + sx * 4 + j] = vsc;
            }
        }
        __syncthreads();

        if (tid < 64) {
            int r = tid;
            float mold = m_s[r];
            float mt = mold;
            for (int c = 0; c < 64; c++) mt = fmaxf(mt, Ps[r * PP + c]);
            float alpha = __expf(mold - mt);
            float sum = 0.f;
            for (int c = 0; c < 64; c++) {
                float pv = __expf(Ps[r * PP + c] - mt);
                Ps[r * PP + c] = pv;
                sum += pv;
            }
            m_s[r] = mt;
            l_s[r] = l_s[r] * alpha + sum;
            al_s[r] = alpha;
        }
        __syncthreads();

        #pragma unroll
        for (int i = 0; i < 8; i++) {
            float al = al_s[py * 8 + i];
            #pragma unroll
            for (int j = 0; j < 8; j++) o[i][j] *= al;
        }
        #pragma unroll 2
        for (int kk = 0; kk < ATT_BN; kk += 4) {
            float4 a[8];
            #pragma unroll
            for (int i = 0; i < 8; i++)
                a[i] = *(float4*)&Ps[(py * 8 + i) * PP + kk];
            #pragma unroll
            for (int k2 = 0; k2 < 4; k2++) {
                float4 b0 = *(float4*)&Vs[(kk + k2) * HDc + px * 8];
                float4 b1 = *(float4*)&Vs[(kk + k2) * HDc + px * 8 + 4];
                #pragma unroll
                for (int i = 0; i < 8; i++) {
                    float av = (k2 == 0) ? a[i].x : (k2 == 1) ? a[i].y
                             : (k2 == 2) ? a[i].z : a[i].w;
                    o[i][0] += av * b0.x; o[i][1] += av * b0.y;
                    o[i][2] += av * b0.z; o[i][3] += av * b0.w;
                    o[i][4] += av * b1.x; o[i][5] += av * b1.y;
                    o[i][6] += av * b1.z; o[i][7] += av * b1.w;
                }
            }
        }
    }

    #pragma unroll
    for (int i = 0; i < 8; i++) {
        int r = py * 8 + i;
        float inv = 1.f / l_s[r];
        size_t base = ((size_t)(b * Sc + q0 + r)) * Hc + hh * HDc + px * 8;
        *(float4*)&O[base] =
            make_float4(o[i][0] * inv, o[i][1] * inv, o[i][2] * inv, o[i][3] * inv);
        *(float4*)&O[base + 4] =
            make_float4(o[i][4] * inv, o[i][5] * inv, o[i][6] * inv, o[i][7] * inv);
    }
}

// ---------------- launch ----------------
extern "C" void kernel_launch(void* const* d_in, const int* in_sizes, int n_in,
                              void* d_out, int out_size)
{
    const float* hidden = (const float*)d_in[0];
    const int*   pos    = (const int*)d_in[1];
    const float* w_qkv  = (const float*)d_in[2];
    const float* w_out  = (const float*)d_in[3];
    float* out = (float*)d_out;

    float *qkv, *Q, *K, *V, *attn;
    cudaGetSymbolAddress((void**)&qkv,  g_qkv);
    cudaGetSymbolAddress((void**)&Q,    g_Q);
    cudaGetSymbolAddress((void**)&K,    g_K);
    cudaGetSymbolAddress((void**)&V,    g_V);
    cudaGetSymbolAddress((void**)&attn, g_attn);

    // 1) qkv = hidden @ w_qkv   [4096,4096] x [4096,12288]  (tf32 tensor cores)
    tf32_gemm_kernel<<<dim3(F3H / TBN, 4096 / TBM), 256>>>(
        hidden, w_qkv, qkv, 4096, F3H, 4096);

    // 2) RoPE + split into Q/K/V [B][NH][S][HD]
    {
        size_t pairs = (size_t)4096 * 6144;
        rope_scatter_kernel<<<(unsigned)(pairs / 256), 256>>>(qkv, pos, Q, K, V);
    }

    // 3) causal flash attention -> attn [B*S][H]
    {
        size_t smem = (size_t)ATTN_SMEM_FLOATS * sizeof(float);
        cudaFuncSetAttribute(attn_kernel,
                             cudaFuncAttributeMaxDynamicSharedMemorySize,
                             (int)smem);
        attn_kernel<<<dim3(Sc / ATT_BM, NHc, Bc), 256, smem>>>(Q, K, V, attn);
    }

    // 4) out = attn @ w_out   [4096,4096] x [4096,4096]  (tf32 tensor cores)
    tf32_gemm_kernel<<<dim3(4096 / TBN, 4096 / TBM), 256>>>(
        attn, w_out, out, 4096, 4096, 4096);
}

// round 3
// speedup vs baseline: 2.9182x; 1.5245x over previous
#include <cuda_runtime.h>
#include <math.h>

// Problem constants
#define Bc 2
#define Sc 2048
#define Hc 4096
#define NHc 16
#define HDc 256
#define F3H 12288   // 3*H

// ---------------- scratch ----------------
__device__ float g_qkv[(size_t)4096 * 12288];     // [B*S][3H]
__device__ float g_Q[(size_t)32 * 2048 * 256];    // [B*NH][S][HD]
__device__ float g_K[(size_t)32 * 2048 * 256];    // [B*NH][S][HD]
__device__ float g_Vt[(size_t)32 * 256 * 2048];   // [B*NH][HD][S]  (transposed!)
__device__ float g_attn[(size_t)4096 * 4096];     // [B*S][H]

// ---------------- helpers ----------------
__device__ __forceinline__ unsigned f2tf32(float x) {
    unsigned u;
    asm("cvt.rna.tf32.f32 %0, %1;" : "=r"(u) : "f"(x));
    return u;
}

__device__ __forceinline__ void mma_tf32(float* d, const unsigned* a, const unsigned* b) {
    asm volatile(
        "mma.sync.aligned.m16n8k8.row.col.f32.tf32.tf32.f32 "
        "{%0,%1,%2,%3}, {%4,%5,%6,%7}, {%8,%9}, {%0,%1,%2,%3};\n"
        : "+f"(d[0]), "+f"(d[1]), "+f"(d[2]), "+f"(d[3])
        : "r"(a[0]), "r"(a[1]), "r"(a[2]), "r"(a[3]), "r"(b[0]), "r"(b[1]));
}

// ---------------- tf32 GEMM, double-buffered ----------------
#define TBM 128
#define TBN 128
#define TBK 32
#define ASTRIDE 137
#define BSTRIDE 132
#define ABUF (TBK * ASTRIDE)
#define BBUF (TBK * BSTRIDE)
#define GEMM_SMEM ((2 * ABUF + 2 * BBUF) * 4)

__global__ __launch_bounds__(256) void tf32_gemm_kernel(
    const float* __restrict__ A, const float* __restrict__ B,
    float* __restrict__ C, int M, int N, int K)
{
    extern __shared__ unsigned sh[];
    unsigned* As = sh;
    unsigned* Bs = sh + 2 * ABUF;

    const int tid  = threadIdx.x;
    const int lane = tid & 31;
    const int wid  = tid >> 5;
    const int wm   = (wid & 1) * 64;
    const int wn   = (wid >> 1) * 32;
    const int lr   = lane >> 2;
    const int lc   = lane & 3;
    const int rowBase = blockIdx.y * TBM;
    const int colBase = blockIdx.x * TBN;
    const int arow = tid >> 3;
    const int acol = (tid & 7) * 4;
    const int brow = tid >> 5;
    const int bcol = (tid & 31) * 4;

    float acc[4][4][4];
    #pragma unroll
    for (int mt = 0; mt < 4; mt++)
        #pragma unroll
        for (int nt = 0; nt < 4; nt++)
            #pragma unroll
            for (int i = 0; i < 4; i++) acc[mt][nt][i] = 0.f;

    float4 ra[4], rb[4];
    // prologue: load tile 0
    #pragma unroll
    for (int i = 0; i < 4; i++)
        ra[i] = *(const float4*)&A[(size_t)(rowBase + arow + i * 32) * K + acol];
    #pragma unroll
    for (int i = 0; i < 4; i++)
        rb[i] = *(const float4*)&B[(size_t)(brow + i * 8) * N + colBase + bcol];

    // stage buf 0
    #pragma unroll
    for (int i = 0; i < 4; i++) {
        As[(acol + 0) * ASTRIDE + arow + i * 32] = f2tf32(ra[i].x);
        As[(acol + 1) * ASTRIDE + arow + i * 32] = f2tf32(ra[i].y);
        As[(acol + 2) * ASTRIDE + arow + i * 32] = f2tf32(ra[i].z);
        As[(acol + 3) * ASTRIDE + arow + i * 32] = f2tf32(ra[i].w);
    }
    #pragma unroll
    for (int i = 0; i < 4; i++)
        *(uint4*)&Bs[(brow + i * 8) * BSTRIDE + bcol] =
            make_uint4(f2tf32(rb[i].x), f2tf32(rb[i].y), f2tf32(rb[i].z), f2tf32(rb[i].w));
    __syncthreads();

    int buf = 0;
    for (int k0 = TBK; k0 < K; k0 += TBK) {
        // prefetch next tile into registers (hides LDG latency under compute)
        #pragma unroll
        for (int i = 0; i < 4; i++)
            ra[i] = *(const float4*)&A[(size_t)(rowBase + arow + i * 32) * K + k0 + acol];
        #pragma unroll
        for (int i = 0; i < 4; i++)
            rb[i] = *(const float4*)&B[(size_t)(k0 + brow + i * 8) * N + colBase + bcol];

        // compute current buffer
        {
            const unsigned* Ab = As + buf * ABUF;
            const unsigned* Bb = Bs + buf * BBUF;
            #pragma unroll
            for (int kk = 0; kk < TBK; kk += 8) {
                unsigned af[4][4], bf[4][2];
                #pragma unroll
                for (int mt = 0; mt < 4; mt++) {
                    int m0 = wm + mt * 16;
                    af[mt][0] = Ab[(kk + lc) * ASTRIDE + m0 + lr];
                    af[mt][1] = Ab[(kk + lc) * ASTRIDE + m0 + lr + 8];
                    af[mt][2] = Ab[(kk + 4 + lc) * ASTRIDE + m0 + lr];
                    af[mt][3] = Ab[(kk + 4 + lc) * ASTRIDE + m0 + lr + 8];
                }
                #pragma unroll
                for (int nt = 0; nt < 4; nt++) {
                    int n0 = wn + nt * 8;
                    bf[nt][0] = Bb[(kk + lc) * BSTRIDE + n0 + lr];
                    bf[nt][1] = Bb[(kk + 4 + lc) * BSTRIDE + n0 + lr];
                }
                #pragma unroll
                for (int mt = 0; mt < 4; mt++)
                    #pragma unroll
                    for (int nt = 0; nt < 4; nt++)
                        mma_tf32(acc[mt][nt], af[mt], bf[nt]);
            }
        }

        // stage next buffer
        {
            unsigned* An = As + (buf ^ 1) * ABUF;
            unsigned* Bn = Bs + (buf ^ 1) * BBUF;
            #pragma unroll
            for (int i = 0; i < 4; i++) {
                An[(acol + 0) * ASTRIDE + arow + i * 32] = f2tf32(ra[i].x);
                An[(acol + 1) * ASTRIDE + arow + i * 32] = f2tf32(ra[i].y);
                An[(acol + 2) * ASTRIDE + arow + i * 32] = f2tf32(ra[i].z);
                An[(acol + 3) * ASTRIDE + arow + i * 32] = f2tf32(ra[i].w);
            }
            #pragma unroll
            for (int i = 0; i < 4; i++)
                *(uint4*)&Bn[(brow + i * 8) * BSTRIDE + bcol] =
                    make_uint4(f2tf32(rb[i].x), f2tf32(rb[i].y), f2tf32(rb[i].z), f2tf32(rb[i].w));
        }
        __syncthreads();
        buf ^= 1;
    }

    // last tile compute
    {
        const unsigned* Ab = As + buf * ABUF;
        const unsigned* Bb = Bs + buf * BBUF;
        #pragma unroll
        for (int kk = 0; kk < TBK; kk += 8) {
            unsigned af[4][4], bf[4][2];
            #pragma unroll
            for (int mt = 0; mt < 4; mt++) {
                int m0 = wm + mt * 16;
                af[mt][0] = Ab[(kk + lc) * ASTRIDE + m0 + lr];
                af[mt][1] = Ab[(kk + lc) * ASTRIDE + m0 + lr + 8];
                af[mt][2] = Ab[(kk + 4 + lc) * ASTRIDE + m0 + lr];
                af[mt][3] = Ab[(kk + 4 + lc) * ASTRIDE + m0 + lr + 8];
            }
            #pragma unroll
            for (int nt = 0; nt < 4; nt++) {
                int n0 = wn + nt * 8;
                bf[nt][0] = Bb[(kk + lc) * BSTRIDE + n0 + lr];
                bf[nt][1] = Bb[(kk + 4 + lc) * BSTRIDE + n0 + lr];
            }
            #pragma unroll
            for (int mt = 0; mt < 4; mt++)
                #pragma unroll
                for (int nt = 0; nt < 4; nt++)
                    mma_tf32(acc[mt][nt], af[mt], bf[nt]);
        }
    }

    // epilogue
    #pragma unroll
    for (int mt = 0; mt < 4; mt++) {
        #pragma unroll
        for (int nt = 0; nt < 4; nt++) {
            int gr = rowBase + wm + mt * 16 + lr;
            int gc = colBase + wn + nt * 8 + 2 * lc;
            *(float2*)&C[(size_t)gr * N + gc] =
                make_float2(acc[mt][nt][0], acc[mt][nt][1]);
            *(float2*)&C[(size_t)(gr + 8) * N + gc] =
                make_float2(acc[mt][nt][2], acc[mt][nt][3]);
        }
    }
}

// ---------------- RoPE for Q/K ----------------
// qkv columns: [0:4096) = q, [4096:8192) = v, [8192:12288) = k
__global__ void rope_qk_kernel(
    const float* __restrict__ qkv, const int* __restrict__ pos_ids,
    float* __restrict__ Q, float* __restrict__ K)
{
    size_t p = (size_t)blockIdx.x * blockDim.x + threadIdx.x;
    int row = (int)(p >> 12);        // b*S + s
    int rem = (int)(p & 4095);
    int isk = rem >> 11;
    int f   = (rem & 2047) * 2;      // 0..4094, within q or k section
    int col = isk ? (8192 + f) : f;
    int b = row >> 11, s = row & 2047;
    int hh = f >> 8, d = f & 255;

    float2 x = *(const float2*)&qkv[(size_t)row * F3H + col];
    float2 y = x;
    if (d < 64) {
        float inv = expf(-(float)d * (9.210340371976184f / 64.f));
        float fr = (float)pos_ids[row] * inv;
        float c, sn;
        sincosf(fr, &sn, &c);
        y.x = x.x * c - x.y * sn;
        y.y = x.y * c + x.x * sn;
    }
    size_t dst = ((size_t)((b * NHc + hh) * Sc + s)) * HDc + d;
    if (isk) *(float2*)&K[dst] = y;
    else     *(float2*)&Q[dst] = y;
}

// ---------------- V transpose: qkv v-section -> Vt [bh][d][s] ----------------
__global__ void vtrans_kernel(const float* __restrict__ qkv, float* __restrict__ Vt)
{
    __shared__ float t[32][33];
    int bh = blockIdx.z;
    int b = bh >> 4, h = bh & 15;
    int s0 = blockIdx.x * 32, d0 = blockIdx.y * 32;
    int tx = threadIdx.x, ty = threadIdx.y;   // (32, 8)
    #pragma unroll
    for (int i = 0; i < 32; i += 8)
        t[ty + i][tx] = qkv[(size_t)(b * Sc + s0 + ty + i) * F3H + Hc + h * HDc + d0 + tx];
    __syncthreads();
    #pragma unroll
    for (int i = 0; i < 32; i += 8)
        Vt[((size_t)(bh * HDc + d0 + ty + i)) * Sc + s0 + tx] = t[tx][ty + i];
}

// ---------------- flash attention, tf32 tensor cores ----------------
#define QKS 260   // Qs/Ks row stride (words)
#define VSS 68    // Vs row stride
#define PSS 68    // Ps row stride
#define ATT2_SMEM_WORDS (64 * QKS * 2 + 256 * VSS + 64 * PSS + 192)

__global__ __launch_bounds__(256) void attn2_kernel(
    const float* __restrict__ Q, const float* __restrict__ K,
    const float* __restrict__ Vt, float* __restrict__ O)
{
    extern __shared__ unsigned sm[];
    unsigned* Qs = sm;                 // [64][QKS] tf32
    unsigned* Ks = Qs + 64 * QKS;      // [64][QKS] tf32
    unsigned* Vs = Ks + 64 * QKS;      // [256][VSS] tf32 (V^T tile: [d][s])
    unsigned* Ps = Vs + 256 * VSS;     // [64][PSS] scores(float) then P(tf32)
    float* m_s  = (float*)(Ps + 64 * PSS);
    float* l_s  = m_s + 64;
    float* al_s = l_s + 64;

    const int tid = threadIdx.x, lane = tid & 31, wid = tid >> 5;
    const int lr = lane >> 2, lc = lane & 3;
    const int wm  = (wid & 3) * 16;      // m offset (QK and PV)
    const int wnq = (wid >> 2) * 32;     // QK n offset
    const int wnp = (wid >> 2) * 128;    // PV n offset
    const int qt = blockIdx.x, hh = blockIdx.y, b = blockIdx.z;
    const int q0 = qt * 64;

    const float* Qg = Q  + (size_t)(b * NHc + hh) * Sc * HDc;
    const float* Kg = K  + (size_t)(b * NHc + hh) * Sc * HDc;
    const float* Vg = Vt + (size_t)(b * NHc + hh) * HDc * Sc;

    // stage Q tile (64 x 256) as tf32
    #pragma unroll
    for (int it = 0; it < 16; it++) {
        int v = tid + it * 256;
        int r = v >> 6, c4 = (v & 63) << 2;
        float4 a = *(const float4*)&Qg[(size_t)(q0 + r) * HDc + c4];
        *(uint4*)&Qs[r * QKS + c4] =
            make_uint4(f2tf32(a.x), f2tf32(a.y), f2tf32(a.z), f2tf32(a.w));
    }
    if (tid < 64) { m_s[tid] = -1e30f; l_s[tid] = 0.f; }

    float o[16][4];
    #pragma unroll
    for (int nt = 0; nt < 16; nt++)
        #pragma unroll
        for (int i = 0; i < 4; i++) o[nt][i] = 0.f;

    for (int kt = 0; kt <= qt; kt++) {
        __syncthreads();   // Q staged / previous PV done
        const int k0 = kt * 64;

        // stage K tile (64 x 256)
        #pragma unroll
        for (int it = 0; it < 16; it++) {
            int v = tid + it * 256;
            int r = v >> 6, c4 = (v & 63) << 2;
            float4 a = *(const float4*)&Kg[(size_t)(k0 + r) * HDc + c4];
            *(uint4*)&Ks[r * QKS + c4] =
                make_uint4(f2tf32(a.x), f2tf32(a.y), f2tf32(a.z), f2tf32(a.w));
        }
        // stage V^T tile (256 x 64)
        #pragma unroll
        for (int it = 0; it < 16; it++) {
            int v = tid + it * 256;
            int r = v >> 4, c4 = (v & 15) << 2;
            float4 a = *(const float4*)&Vg[(size_t)r * Sc + k0 + c4];
            *(uint4*)&Vs[r * VSS + c4] =
                make_uint4(f2tf32(a.x), f2tf32(a.y), f2tf32(a.z), f2tf32(a.w));
        }
        __syncthreads();

        // scores: S = Q K^T  (per warp: 16 x 32)
        float sacc[4][4];
        #pragma unroll
        for (int nt = 0; nt < 4; nt++)
            #pragma unroll
            for (int i = 0; i < 4; i++) sacc[nt][i] = 0.f;

        #pragma unroll 4
        for (int kk = 0; kk < HDc; kk += 8) {
            unsigned af[4];
            af[0] = Qs[(wm + lr) * QKS + kk + lc];
            af[1] = Qs[(wm + lr + 8) * QKS + kk + lc];
            af[2] = Qs[(wm + lr) * QKS + kk + 4 + lc];
            af[3] = Qs[(wm + lr + 8) * QKS + kk + 4 + lc];
            #pragma unroll
            for (int nt = 0; nt < 4; nt++) {
                unsigned bf[2];
                bf[0] = Ks[(wnq + nt * 8 + lr) * QKS + kk + lc];
                bf[1] = Ks[(wnq + nt * 8 + lr) * QKS + kk + 4 + lc];
                mma_tf32(sacc[nt], af, bf);
            }
        }

        // scale + mask + write scores (fp32) to Ps
        {
            float* Pf = (float*)Ps;
            const bool diag = (kt == qt);
            const int r0 = wm + lr, r1 = wm + lr + 8;
            #pragma unroll
            for (int nt = 0; nt < 4; nt++) {
                int cc = wnq + nt * 8 + 2 * lc;
                float s0 = sacc[nt][0] * 0.0625f;
                float s1 = sacc[nt][1] * 0.0625f;
                float s2 = sacc[nt][2] * 0.0625f;
                float s3 = sacc[nt][3] * 0.0625f;
                if (diag) {
                    if (cc     > r0) s0 = -1e30f;
                    if (cc + 1 > r0) s1 = -1e30f;
                    if (cc     > r1) s2 = -1e30f;
                    if (cc + 1 > r1) s3 = -1e30f;
                }
                Pf[r0 * PSS + cc] = s0;  Pf[r0 * PSS + cc + 1] = s1;
                Pf[r1 * PSS + cc] = s2;  Pf[r1 * PSS + cc + 1] = s3;
            }
        }
        __syncthreads();

        // online softmax: 4 threads per row
        {
            float* Pf = (float*)Ps;
            int r = tid >> 2, part = tid & 3;
            int cb = part * 16;
            float mx = -1e30f;
            #pragma unroll
            for (int j = 0; j < 16; j++) mx = fmaxf(mx, Pf[r * PSS + cb + j]);
            mx = fmaxf(mx, __shfl_xor_sync(0xffffffffu, mx, 1));
            mx = fmaxf(mx, __shfl_xor_sync(0xffffffffu, mx, 2));
            float mold = m_s[r];
            float mnew = fmaxf(mold, mx);
            float sum = 0.f;
            #pragma unroll
            for (int j = 0; j < 16; j++) {
                float pv = __expf(Pf[r * PSS + cb + j] - mnew);
                sum += pv;
                Ps[r * PSS + cb + j] = f2tf32(pv);
            }
            sum += __shfl_xor_sync(0xffffffffu, sum, 1);
            sum += __shfl_xor_sync(0xffffffffu, sum, 2);
            if (part == 0) {
                float alpha = __expf(mold - mnew);
                m_s[r] = mnew;
                l_s[r] = l_s[r] * alpha + sum;
                al_s[r] = alpha;
            }
        }
        __syncthreads();

        // rescale O accumulators
        {
            float a0 = al_s[wm + lr], a1 = al_s[wm + lr + 8];
            #pragma unroll
            for (int nt = 0; nt < 16; nt++) {
                o[nt][0] *= a0; o[nt][1] *= a0;
                o[nt][2] *= a1; o[nt][3] *= a1;
            }
        }

        // O += P V  (per warp: 16 x 128)
        #pragma unroll 2
        for (int kk = 0; kk < 64; kk += 8) {
            unsigned af[4];
            af[0] = Ps[(wm + lr) * PSS + kk + lc];
            af[1] = Ps[(wm + lr + 8) * PSS + kk + lc];
            af[2] = Ps[(wm + lr) * PSS + kk + 4 + lc];
            af[3] = Ps[(wm + lr + 8) * PSS + kk + 4 + lc];
            #pragma unroll
            for (int nt = 0; nt < 16; nt++) {
                unsigned bf[2];
                bf[0] = Vs[(wnp + nt * 8 + lr) * VSS + kk + lc];
                bf[1] = Vs[(wnp + nt * 8 + lr) * VSS + kk + 4 + lc];
                mma_tf32(o[nt], af, bf);
            }
        }
    }

    // epilogue: normalize + write [B*S][H]
    {
        float i0 = 1.f / l_s[wm + lr];
        float i1 = 1.f / l_s[wm + lr + 8];
        #pragma unroll
        for (int nt = 0; nt < 16; nt++) {
            size_t base0 = ((size_t)(b * Sc + q0 + wm + lr)) * Hc + hh * HDc + wnp + nt * 8 + 2 * lc;
            size_t base1 = ((size_t)(b * Sc + q0 + wm + lr + 8)) * Hc + hh * HDc + wnp + nt * 8 + 2 * lc;
            *(float2*)&O[base0] = make_float2(o[nt][0] * i0, o[nt][1] * i0);
            *(float2*)&O[base1] = make_float2(o[nt][2] * i1, o[nt][3] * i1);
        }
    }
}

// ---------------- launch ----------------
extern "C" void kernel_launch(void* const* d_in, const int* in_sizes, int n_in,
                              void* d_out, int out_size)
{
    const float* hidden = (const float*)d_in[0];
    const int*   pos    = (const int*)d_in[1];
    const float* w_qkv  = (const float*)d_in[2];
    const float* w_out  = (const float*)d_in[3];
    float* out = (float*)d_out;

    float *qkv, *Q, *K, *Vt, *attn;
    cudaGetSymbolAddress((void**)&qkv,  g_qkv);
    cudaGetSymbolAddress((void**)&Q,    g_Q);
    cudaGetSymbolAddress((void**)&K,    g_K);
    cudaGetSymbolAddress((void**)&Vt,   g_Vt);
    cudaGetSymbolAddress((void**)&attn, g_attn);

    cudaFuncSetAttribute(tf32_gemm_kernel,
                         cudaFuncAttributeMaxDynamicSharedMemorySize, GEMM_SMEM);
    cudaFuncSetAttribute(attn2_kernel,
                         cudaFuncAttributeMaxDynamicSharedMemorySize,
                         (int)(ATT2_SMEM_WORDS * sizeof(unsigned)));

    // 1) qkv = hidden @ w_qkv
    tf32_gemm_kernel<<<dim3(F3H / TBN, 4096 / TBM), 256, GEMM_SMEM>>>(
        hidden, w_qkv, qkv, 4096, F3H, 4096);

    // 2a) RoPE on q,k sections -> Q, K [B*NH][S][HD]
    rope_qk_kernel<<<65536, 256>>>(qkv, pos, Q, K);
    // 2b) transpose v section -> Vt [B*NH][HD][S]
    vtrans_kernel<<<dim3(Sc / 32, HDc / 32, 32), dim3(32, 8)>>>(qkv, Vt);

    // 3) tf32 flash attention -> attn [B*S][H]
    attn2_kernel<<<dim3(Sc / 64, NHc, Bc), 256,
                   ATT2_SMEM_WORDS * sizeof(unsigned)>>>(Q, K, Vt, attn);

    // 4) out = attn @ w_out
    tf32_gemm_kernel<<<dim3(4096 / TBN, 4096 / TBM), 256, GEMM_SMEM>>>(
        attn, w_out, out, 4096, 4096, 4096);
}

// round 5
// speedup vs baseline: 3.4465x; 1.1810x over previous
#include <cuda_runtime.h>
#include <cuda_fp16.h>
#include <math.h>
#include <stdint.h>

// Problem constants
#define Bc 2
#define Sc 2048
#define Hc 4096
#define NHc 16
#define HDc 256
#define F3H 12288   // 3*H

// ---------------- scratch ----------------
__device__ float g_qkv[(size_t)4096 * 12288];     // [B*S][3H]
__device__ float g_Q[(size_t)32 * 2048 * 256];    // [B*NH][S][HD]
__device__ float g_K[(size_t)32 * 2048 * 256];
__device__ float g_Vt[(size_t)32 * 256 * 2048];   // [B*NH][HD][S]
__device__ float g_attn[(size_t)4096 * 4096];     // [B*S][H]

// ---------------- helpers ----------------
__device__ __forceinline__ uint32_t smem_u32(const void* p) {
    uint32_t a;
    asm("{ .reg .u64 t; cvta.to.shared.u64 t, %1; cvt.u32.u64 %0, t; }"
        : "=r"(a) : "l"(p));
    return a;
}
__device__ __forceinline__ unsigned pack2(float x, float y) {
    __half2 h = __floats2half2_rn(x, y);
    return *(unsigned*)&h;
}
__device__ __forceinline__ unsigned f2tf32(float x) {
    unsigned u;
    asm("cvt.rna.tf32.f32 %0, %1;" : "=r"(u) : "f"(x));
    return u;
}
__device__ __forceinline__ void mma_tf32(float* d, const unsigned* a, const unsigned* b) {
    asm volatile(
        "mma.sync.aligned.m16n8k8.row.col.f32.tf32.tf32.f32 "
        "{%0,%1,%2,%3}, {%4,%5,%6,%7}, {%8,%9}, {%0,%1,%2,%3};\n"
        : "+f"(d[0]), "+f"(d[1]), "+f"(d[2]), "+f"(d[3])
        : "r"(a[0]), "r"(a[1]), "r"(a[2]), "r"(a[3]), "r"(b[0]), "r"(b[1]));
}
__device__ __forceinline__ void mma_f16(float* d, const unsigned* a, const unsigned* b) {
    asm volatile(
        "mma.sync.aligned.m16n8k16.row.col.f32.f16.f16.f32 "
        "{%0,%1,%2,%3}, {%4,%5,%6,%7}, {%8,%9}, {%0,%1,%2,%3};\n"
        : "+f"(d[0]), "+f"(d[1]), "+f"(d[2]), "+f"(d[3])
        : "r"(a[0]), "r"(a[1]), "r"(a[2]), "r"(a[3]), "r"(b[0]), "r"(b[1]));
}
#define LDSM_X4(r0, r1, r2, r3, addr) \
    asm volatile("ldmatrix.sync.aligned.m8n8.x4.shared.b16 {%0,%1,%2,%3}, [%4];" \
        : "=r"(r0), "=r"(r1), "=r"(r2), "=r"(r3) : "r"(addr))
#define LDSM_X4_T(r0, r1, r2, r3, addr) \
    asm volatile("ldmatrix.sync.aligned.m8n8.x4.trans.shared.b16 {%0,%1,%2,%3}, [%4];" \
        : "=r"(r0), "=r"(r1), "=r"(r2), "=r"(r3) : "r"(addr))

// ================= fp16 tensor-core GEMM =================
// C[M x N] = A[M x K] * B[K x N], A,B,C fp32 row-major; compute in fp16 mma k16.
// tile 128x128x32, 256 threads (8 warps: 2x4 of 64x32)
//
// A smem layout: pair-row p=m>>1 owns a 128B row of 8 chunks (16B each):
//   chunk(m, kc) = ((m&1)*4 + kc) ^ (p & 7), kc = k/8 in 0..3
// B smem layout: row k owns 256B (16 chunks): chunk(k, nc) = nc ^ (k & 7)
#define TBM 128
#define TBN 128
#define TBK 32
#define A_STAGE 8192
#define B_STAGE 8192

__global__ __launch_bounds__(256) void f16_gemm_kernel(
    const float* __restrict__ A, const float* __restrict__ B,
    float* __restrict__ C, int N, int K, int colTiles)
{
    __shared__ char sm[2 * A_STAGE + 2 * B_STAGE];  // [A0][A1][B0][B1]
    char* smA = sm;
    char* smB = sm + 2 * A_STAGE;
    const uint32_t uA = smem_u32(smA);
    const uint32_t uB = smem_u32(smB);

    const int tid  = threadIdx.x;
    const int lane = tid & 31;
    const int wid  = tid >> 5;
    const int wm   = (wid & 1) * 64;
    const int wn   = (wid >> 1) * 32;

    // supertile rasterization (8 row-tiles per group)
    const int bid = blockIdx.x;
    const int per = 8 * colTiles;
    const int rem = bid % per;
    const int rt = (bid / per) * 8 + (rem & 7);
    const int ct = rem >> 3;
    const int rowBase = rt * TBM;
    const int colBase = ct * TBN;

    // ---- staging geometry ----
    const int sm_m = tid >> 1;            // A row 0..127
    const int sk0  = (tid & 1) * 2;       // A chunk base (0 or 2)
    const int sb_k = tid >> 3;            // B row 0..31
    const int sb_n = tid & 7;             // B chunk base
    uint32_t stsA[2], stsB[2];
    #pragma unroll
    for (int j = 0; j < 2; j++) {
        int kc = sk0 + j;
        int ch = (((sm_m & 1) << 2) + kc) ^ ((sm_m >> 1) & 7);
        stsA[j] = (uint32_t)((sm_m >> 1) * 128 + ch * 16);
        int nc = sb_n + 8 * j;
        stsB[j] = (uint32_t)(sb_k * 256 + (nc ^ (sb_k & 7)) * 16);
    }
    const float* Arow = A + (size_t)(rowBase + sm_m) * K + sk0 * 8;
    const float* Brow = B + (size_t)sb_k * N + colBase + sb_n * 8;

    // ---- fragment-load geometry ----
    // A: mat = lane>>3; m_loc = wm + (mat&1)*8 + (lane&7); kc = 2s + (mat>>1)
    uint32_t ldA[2];
    {
        int m_loc = wm + ((lane >> 3) & 1) * 8 + (lane & 7);
        #pragma unroll
        for (int s = 0; s < 2; s++) {
            int kc = 2 * s + (lane >> 4);
            int ch = (((m_loc & 1) << 2) + kc) ^ ((m_loc >> 1) & 7);
            ldA[s] = (uint32_t)((m_loc >> 1) * 128 + ch * 16);
        }
    }
    // B: mat = lane>>3; k_loc = 16s + (mat>>1)*8 + (lane&7); nc = wn/8 + 2ng + (mat&1)
    uint32_t ldB[2];
    {
        int k_low = ((lane >> 4)) * 8 + (lane & 7);
        int nc = (wn >> 3) + ((lane >> 3) & 1);
        #pragma unroll
        for (int s = 0; s < 2; s++) {
            int k_loc = 16 * s + k_low;
            ldB[s] = (uint32_t)(k_loc * 256 + ((nc ^ (k_loc & 7)) * 16));
        }
    }

    float acc[4][4][4];
    #pragma unroll
    for (int mt = 0; mt < 4; mt++)
        #pragma unroll
        for (int nt = 0; nt < 4; nt++)
            #pragma unroll
            for (int i = 0; i < 4; i++) acc[mt][nt][i] = 0.f;

    const int nk = K / TBK;
    float4 ra[2][2], rb[2][2];

    // prologue: load tile 0
    #pragma unroll
    for (int j = 0; j < 2; j++) {
        ra[j][0] = *(const float4*)(Arow + j * 8);
        ra[j][1] = *(const float4*)(Arow + j * 8 + 4);
        rb[j][0] = *(const float4*)(Brow + j * 64);
        rb[j][1] = *(const float4*)(Brow + j * 64 + 4);
    }
    // stage buf0
    #pragma unroll
    for (int j = 0; j < 2; j++) {
        *(uint4*)(smA + stsA[j]) = make_uint4(
            pack2(ra[j][0].x, ra[j][0].y), pack2(ra[j][0].z, ra[j][0].w),
            pack2(ra[j][1].x, ra[j][1].y), pack2(ra[j][1].z, ra[j][1].w));
        *(uint4*)(smB + stsB[j]) = make_uint4(
            pack2(rb[j][0].x, rb[j][0].y), pack2(rb[j][0].z, rb[j][0].w),
            pack2(rb[j][1].x, rb[j][1].y), pack2(rb[j][1].z, rb[j][1].w));
    }
    __syncthreads();

    int buf = 0;
    for (int c = 0; c < nk; c++) {
        // prefetch next tile
        if (c + 1 < nk) {
            const float* Ap = Arow + (size_t)(c + 1) * TBK;
            const float* Bp = Brow + (size_t)(c + 1) * TBK * N;
            #pragma unroll
            for (int j = 0; j < 2; j++) {
                ra[j][0] = *(const float4*)(Ap + j * 8);
                ra[j][1] = *(const float4*)(Ap + j * 8 + 4);
                rb[j][0] = *(const float4*)(Bp + j * 64);
                rb[j][1] = *(const float4*)(Bp + j * 64 + 4);
            }
        }

        // compute current buffer
        const uint32_t aoff = uA + buf * A_STAGE;
        const uint32_t boff = uB + buf * B_STAGE;
        #pragma unroll
        for (int s = 0; s < 2; s++) {
            unsigned af[4][4];
            #pragma unroll
            for (int mt = 0; mt < 4; mt++)
                LDSM_X4(af[mt][0], af[mt][1], af[mt][2], af[mt][3],
                        aoff + ldA[s] + mt * 1024);
            unsigned bf[4][2];
            #pragma unroll
            for (int ng = 0; ng < 2; ng++) {
                unsigned r0, r1, r2, r3;
                LDSM_X4_T(r0, r1, r2, r3, (boff + ldB[s]) ^ (ng * 32));
                bf[2 * ng + 0][0] = r0; bf[2 * ng + 0][1] = r2;
                bf[2 * ng + 1][0] = r1; bf[2 * ng + 1][1] = r3;
            }
            #pragma unroll
            for (int mt = 0; mt < 4; mt++)
                #pragma unroll
                for (int nt = 0; nt < 4; nt++)
                    mma_f16(acc[mt][nt], af[mt], bf[nt]);
        }

        // stage next buffer
        if (c + 1 < nk) {
            char* dA = smA + (buf ^ 1) * A_STAGE;
            char* dB = smB + (buf ^ 1) * B_STAGE;
            #pragma unroll
            for (int j = 0; j < 2; j++) {
                *(uint4*)(dA + stsA[j]) = make_uint4(
                    pack2(ra[j][0].x, ra[j][0].y), pack2(ra[j][0].z, ra[j][0].w),
                    pack2(ra[j][1].x, ra[j][1].y), pack2(ra[j][1].z, ra[j][1].w));
                *(uint4*)(dB + stsB[j]) = make_uint4(
                    pack2(rb[j][0].x, rb[j][0].y), pack2(rb[j][0].z, rb[j][0].w),
                    pack2(rb[j][1].x, rb[j][1].y), pack2(rb[j][1].z, rb[j][1].w));
            }
            __syncthreads();
        }
        buf ^= 1;
    }

    // epilogue
    const int lr = lane >> 2, lc = lane & 3;
    #pragma unroll
    for (int mt = 0; mt < 4; mt++) {
        #pragma unroll
        for (int nt = 0; nt < 4; nt++) {
            int gr = rowBase + wm + mt * 16 + lr;
            int gc = colBase + wn + nt * 8 + 2 * lc;
            *(float2*)&C[(size_t)gr * N + gc] =
                make_float2(acc[mt][nt][0], acc[mt][nt][1]);
            *(float2*)&C[(size_t)(gr + 8) * N + gc] =
                make_float2(acc[mt][nt][2], acc[mt][nt][3]);
        }
    }
}

// ================= RoPE for Q/K =================
// qkv columns: [0:4096)=q, [4096:8192)=v, [8192:12288)=k
__global__ void rope_qk_kernel(
    const float* __restrict__ qkv, const int* __restrict__ pos_ids,
    float* __restrict__ Q, float* __restrict__ K)
{
    size_t p = (size_t)blockIdx.x * blockDim.x + threadIdx.x;
    int row = (int)(p >> 12);
    int rem = (int)(p & 4095);
    int isk = rem >> 11;
    int f   = (rem & 2047) * 2;
    int col = isk ? (8192 + f) : f;
    int b = row >> 11, s = row & 2047;
    int hh = f >> 8, d = f & 255;

    float2 x = *(const float2*)&qkv[(size_t)row * F3H + col];
    float2 y = x;
    if (d < 64) {
        float inv = expf(-(float)d * (9.210340371976184f / 64.f));
        float fr = (float)pos_ids[row] * inv;
        float c, sn;
        sincosf(fr, &sn, &c);
        y.x = x.x * c - x.y * sn;
        y.y = x.y * c + x.x * sn;
    }
    size_t dst = ((size_t)((b * NHc + hh) * Sc + s)) * HDc + d;
    if (isk) *(float2*)&K[dst] = y;
    else     *(float2*)&Q[dst] = y;
}

// ================= V transpose =================
__global__ void vtrans_kernel(const float* __restrict__ qkv, float* __restrict__ Vt)
{
    __shared__ float t[32][33];
    int bh = blockIdx.z;
    int b = bh >> 4, h = bh & 15;
    int s0 = blockIdx.x * 32, d0 = blockIdx.y * 32;
    int tx = threadIdx.x, ty = threadIdx.y;
    #pragma unroll
    for (int i = 0; i < 32; i += 8)
        t[ty + i][tx] = qkv[(size_t)(b * Sc + s0 + ty + i) * F3H + Hc + h * HDc + d0 + tx];
    __syncthreads();
    #pragma unroll
    for (int i = 0; i < 32; i += 8)
        Vt[((size_t)(bh * HDc + d0 + ty + i)) * Sc + s0 + tx] = t[tx][ty + i];
}

// ================= flash attention, tf32 legacy mma =================
#define QKS 260
#define VSS 68
#define PSS 68
#define ATT2_SMEM_WORDS (64 * QKS * 2 + 256 * VSS + 64 * PSS + 192)

__global__ __launch_bounds__(256) void attn2_kernel(
    const float* __restrict__ Q, const float* __restrict__ K,
    const float* __restrict__ Vt, float* __restrict__ O)
{
    extern __shared__ unsigned smx[];
    unsigned* Qs = smx;
    unsigned* Ks = Qs + 64 * QKS;
    unsigned* Vs = Ks + 64 * QKS;
    unsigned* Ps = Vs + 256 * VSS;
    float* m_s  = (float*)(Ps + 64 * PSS);
    float* l_s  = m_s + 64;
    float* al_s = l_s + 64;

    const int tid = threadIdx.x, lane = tid & 31, wid = tid >> 5;
    const int lr = lane >> 2, lc = lane & 3;
    const int wm  = (wid & 3) * 16;
    const int wnq = (wid >> 2) * 32;
    const int wnp = (wid >> 2) * 128;
    const int qt = blockIdx.x, hh = blockIdx.y, b = blockIdx.z;
    const int q0 = qt * 64;

    const float* Qg = Q  + (size_t)(b * NHc + hh) * Sc * HDc;
    const float* Kg = K  + (size_t)(b * NHc + hh) * Sc * HDc;
    const float* Vg = Vt + (size_t)(b * NHc + hh) * HDc * Sc;

    #pragma unroll
    for (int it = 0; it < 16; it++) {
        int v = tid + it * 256;
        int r = v >> 6, c4 = (v & 63) << 2;
        float4 a = *(const float4*)&Qg[(size_t)(q0 + r) * HDc + c4];
        *(uint4*)&Qs[r * QKS + c4] =
            make_uint4(f2tf32(a.x), f2tf32(a.y), f2tf32(a.z), f2tf32(a.w));
    }
    if (tid < 64) { m_s[tid] = -1e30f; l_s[tid] = 0.f; }

    float o[16][4];
    #pragma unroll
    for (int nt = 0; nt < 16; nt++)
        #pragma unroll
        for (int i = 0; i < 4; i++) o[nt][i] = 0.f;

    for (int kt = 0; kt <= qt; kt++) {
        __syncthreads();
        const int k0 = kt * 64;

        #pragma unroll
        for (int it = 0; it < 16; it++) {
            int v = tid + it * 256;
            int r = v >> 6, c4 = (v & 63) << 2;
            float4 a = *(const float4*)&Kg[(size_t)(k0 + r) * HDc + c4];
            *(uint4*)&Ks[r * QKS + c4] =
                make_uint4(f2tf32(a.x), f2tf32(a.y), f2tf32(a.z), f2tf32(a.w));
        }
        #pragma unroll
        for (int it = 0; it < 16; it++) {
            int v = tid + it * 256;
            int r = v >> 4, c4 = (v & 15) << 2;
            float4 a = *(const float4*)&Vg[(size_t)r * Sc + k0 + c4];
            *(uint4*)&Vs[r * VSS + c4] =
                make_uint4(f2tf32(a.x), f2tf32(a.y), f2tf32(a.z), f2tf32(a.w));
        }
        __syncthreads();

        float sacc[4][4];
        #pragma unroll
        for (int nt = 0; nt < 4; nt++)
            #pragma unroll
            for (int i = 0; i < 4; i++) sacc[nt][i] = 0.f;

        #pragma unroll 4
        for (int kk = 0; kk < HDc; kk += 8) {
            unsigned af[4];
            af[0] = Qs[(wm + lr) * QKS + kk + lc];
            af[1] = Qs[(wm + lr + 8) * QKS + kk + lc];
            af[2] = Qs[(wm + lr) * QKS + kk + 4 + lc];
            af[3] = Qs[(wm + lr + 8) * QKS + kk + 4 + lc];
            #pragma unroll
            for (int nt = 0; nt < 4; nt++) {
                unsigned bf[2];
                bf[0] = Ks[(wnq + nt * 8 + lr) * QKS + kk + lc];
                bf[1] = Ks[(wnq + nt * 8 + lr) * QKS + kk + 4 + lc];
                mma_tf32(sacc[nt], af, bf);
            }
        }

        {
            float* Pf = (float*)Ps;
            const bool diag = (kt == qt);
            const int r0 = wm + lr, r1 = wm + lr + 8;
            #pragma unroll
            for (int nt = 0; nt < 4; nt++) {
                int cc = wnq + nt * 8 + 2 * lc;
                float s0 = sacc[nt][0] * 0.0625f;
                float s1 = sacc[nt][1] * 0.0625f;
                float s2 = sacc[nt][2] * 0.0625f;
                float s3 = sacc[nt][3] * 0.0625f;
                if (diag) {
                    if (cc     > r0) s0 = -1e30f;
                    if (cc + 1 > r0) s1 = -1e30f;
                    if (cc     > r1) s2 = -1e30f;
                    if (cc + 1 > r1) s3 = -1e30f;
                }
                Pf[r0 * PSS + cc] = s0;  Pf[r0 * PSS + cc + 1] = s1;
                Pf[r1 * PSS + cc] = s2;  Pf[r1 * PSS + cc + 1] = s3;
            }
        }
        __syncthreads();

        {
            float* Pf = (float*)Ps;
            int r = tid >> 2, part = tid & 3;
            int cb = part * 16;
            float mx = -1e30f;
            #pragma unroll
            for (int j = 0; j < 16; j++) mx = fmaxf(mx, Pf[r * PSS + cb + j]);
            mx = fmaxf(mx, __shfl_xor_sync(0xffffffffu, mx, 1));
            mx = fmaxf(mx, __shfl_xor_sync(0xffffffffu, mx, 2));
            float mold = m_s[r];
            float mnew = fmaxf(mold, mx);
            float sum = 0.f;
            #pragma unroll
            for (int j = 0; j < 16; j++) {
                float pv = __expf(Pf[r * PSS + cb + j] - mnew);
                sum += pv;
                Ps[r * PSS + cb + j] = f2tf32(pv);
            }
            sum += __shfl_xor_sync(0xffffffffu, sum, 1);
            sum += __shfl_xor_sync(0xffffffffu, sum, 2);
            if (part == 0) {
                float alpha = __expf(mold - mnew);
                m_s[r] = mnew;
                l_s[r] = l_s[r] * alpha + sum;
                al_s[r] = alpha;
            }
        }
        __syncthreads();

        {
            float a0 = al_s[wm + lr], a1 = al_s[wm + lr + 8];
            #pragma unroll
            for (int nt = 0; nt < 16; nt++) {
                o[nt][0] *= a0; o[nt][1] *= a0;
                o[nt][2] *= a1; o[nt][3] *= a1;
            }
        }

        #pragma unroll 2
        for (int kk = 0; kk < 64; kk += 8) {
            unsigned af[4];
            af[0] = Ps[(wm + lr) * PSS + kk + lc];
            af[1] = Ps[(wm + lr + 8) * PSS + kk + lc];
            af[2] = Ps[(wm + lr) * PSS + kk + 4 + lc];
            af[3] = Ps[(wm + lr + 8) * PSS + kk + 4 + lc];
            #pragma unroll
            for (int nt = 0; nt < 16; nt++) {
                unsigned bf[2];
                bf[0] = Vs[(wnp + nt * 8 + lr) * VSS + kk + lc];
                bf[1] = Vs[(wnp + nt * 8 + lr) * VSS + kk + 4 + lc];
                mma_tf32(o[nt], af, bf);
            }
        }
    }

    {
        float i0 = 1.f / l_s[wm + lr];
        float i1 = 1.f / l_s[wm + lr + 8];
        #pragma unroll
        for (int nt = 0; nt < 16; nt++) {
            size_t base0 = ((size_t)(b * Sc + q0 + wm + lr)) * Hc + hh * HDc + wnp + nt * 8 + 2 * lc;
            size_t base1 = ((size_t)(b * Sc + q0 + wm + lr + 8)) * Hc + hh * HDc + wnp + nt * 8 + 2 * lc;
            *(float2*)&O[base0] = make_float2(o[nt][0] * i0, o[nt][1] * i0);
            *(float2*)&O[base1] = make_float2(o[nt][2] * i1, o[nt][3] * i1);
        }
    }
}

// ================= launch =================
extern "C" void kernel_launch(void* const* d_in, const int* in_sizes, int n_in,
                              void* d_out, int out_size)
{
    const float* hidden = (const float*)d_in[0];
    const int*   pos    = (const int*)d_in[1];
    const float* w_qkv  = (const float*)d_in[2];
    const float* w_out  = (const float*)d_in[3];
    float* out = (float*)d_out;

    float *qkv, *Q, *K, *Vt, *attn;
    cudaGetSymbolAddress((void**)&qkv,  g_qkv);
    cudaGetSymbolAddress((void**)&Q,    g_Q);
    cudaGetSymbolAddress((void**)&K,    g_K);
    cudaGetSymbolAddress((void**)&Vt,   g_Vt);
    cudaGetSymbolAddress((void**)&attn, g_attn);

    cudaFuncSetAttribute(attn2_kernel,
                         cudaFuncAttributeMaxDynamicSharedMemorySize,
                         (int)(ATT2_SMEM_WORDS * sizeof(unsigned)));

    // 1) qkv = hidden @ w_qkv   (fp16 mma, B row-major via ldmatrix.trans)
    f16_gemm_kernel<<<(4096 / TBM) * (F3H / TBN), 256>>>(
        hidden, w_qkv, qkv, F3H, 4096, F3H / TBN);

    // 2) RoPE + V transpose
    rope_qk_kernel<<<65536, 256>>>(qkv, pos, Q, K);
    vtrans_kernel<<<dim3(Sc / 32, HDc / 32, 32), dim3(32, 8)>>>(qkv, Vt);

    // 3) flash attention (tf32)
    attn2_kernel<<<dim3(Sc / 64, NHc, Bc), 256,
                   ATT2_SMEM_WORDS * sizeof(unsigned)>>>(Q, K, Vt, attn);

    // 4) out = attn @ w_out   (fp16 mma)
    f16_gemm_kernel<<<(4096 / TBM) * (Hc / TBN), 256>>>(
        attn, w_out, out, Hc, 4096, Hc / TBN);
}

// round 6
// speedup vs baseline: 3.6464x; 1.0580x over previous
#include <cuda_runtime.h>
#include <cuda_fp16.h>
#include <math.h>
#include <stdint.h>

// Problem constants
#define Bc 2
#define Sc 2048
#define Hc 4096
#define NHc 16
#define HDc 256
#define F3H 12288   // 3*H

// ---------------- scratch ----------------
__device__ float  g_qkv[(size_t)4096 * 12288];    // [B*S][3H]
__device__ __half g_Qh[(size_t)32 * 2048 * 256];  // [B*NH][S][HD] fp16
__device__ __half g_Kh[(size_t)32 * 2048 * 256];
__device__ __half g_Vh[(size_t)32 * 2048 * 256];
__device__ float  g_attn[(size_t)4096 * 4096];    // [B*S][H]

// ---------------- helpers ----------------
__device__ __forceinline__ uint32_t smem_u32(const void* p) {
    uint32_t a;
    asm("{ .reg .u64 t; cvta.to.shared.u64 t, %1; cvt.u32.u64 %0, t; }"
        : "=r"(a) : "l"(p));
    return a;
}
__device__ __forceinline__ unsigned pack2(float x, float y) {
    __half2 h = __floats2half2_rn(x, y);
    return *(unsigned*)&h;
}
__device__ __forceinline__ void mma_f16(float* d, const unsigned* a, const unsigned* b) {
    asm volatile(
        "mma.sync.aligned.m16n8k16.row.col.f32.f16.f16.f32 "
        "{%0,%1,%2,%3}, {%4,%5,%6,%7}, {%8,%9}, {%0,%1,%2,%3};\n"
        : "+f"(d[0]), "+f"(d[1]), "+f"(d[2]), "+f"(d[3])
        : "r"(a[0]), "r"(a[1]), "r"(a[2]), "r"(a[3]), "r"(b[0]), "r"(b[1]));
}
#define LDSM_X4(r0, r1, r2, r3, addr) \
    asm volatile("ldmatrix.sync.aligned.m8n8.x4.shared.b16 {%0,%1,%2,%3}, [%4];" \
        : "=r"(r0), "=r"(r1), "=r"(r2), "=r"(r3) : "r"(addr))
#define LDSM_X4_T(r0, r1, r2, r3, addr) \
    asm volatile("ldmatrix.sync.aligned.m8n8.x4.trans.shared.b16 {%0,%1,%2,%3}, [%4];" \
        : "=r"(r0), "=r"(r1), "=r"(r2), "=r"(r3) : "r"(addr))

// ================= fp16 tensor-core GEMM (unchanged from R5) =================
#define TBM 128
#define TBN 128
#define TBK 32
#define A_STAGE 8192
#define B_STAGE 8192

__global__ __launch_bounds__(256) void f16_gemm_kernel(
    const float* __restrict__ A, const float* __restrict__ B,
    float* __restrict__ C, int N, int K, int colTiles)
{
    __shared__ char sm[2 * A_STAGE + 2 * B_STAGE];
    char* smA = sm;
    char* smB = sm + 2 * A_STAGE;
    const uint32_t uA = smem_u32(smA);
    const uint32_t uB = smem_u32(smB);

    const int tid  = threadIdx.x;
    const int lane = tid & 31;
    const int wid  = tid >> 5;
    const int wm   = (wid & 1) * 64;
    const int wn   = (wid >> 1) * 32;

    const int bid = blockIdx.x;
    const int per = 8 * colTiles;
    const int rem = bid % per;
    const int rt = (bid / per) * 8 + (rem & 7);
    const int ct = rem >> 3;
    const int rowBase = rt * TBM;
    const int colBase = ct * TBN;

    const int sm_m = tid >> 1;
    const int sk0  = (tid & 1) * 2;
    const int sb_k = tid >> 3;
    const int sb_n = tid & 7;
    uint32_t stsA[2], stsB[2];
    #pragma unroll
    for (int j = 0; j < 2; j++) {
        int kc = sk0 + j;
        int ch = (((sm_m & 1) << 2) + kc) ^ ((sm_m >> 1) & 7);
        stsA[j] = (uint32_t)((sm_m >> 1) * 128 + ch * 16);
        int nc = sb_n + 8 * j;
        stsB[j] = (uint32_t)(sb_k * 256 + (nc ^ (sb_k & 7)) * 16);
    }
    const float* Arow = A + (size_t)(rowBase + sm_m) * K + sk0 * 8;
    const float* Brow = B + (size_t)sb_k * N + colBase + sb_n * 8;

    uint32_t ldA[2];
    {
        int m_loc = wm + ((lane >> 3) & 1) * 8 + (lane & 7);
        #pragma unroll
        for (int s = 0; s < 2; s++) {
            int kc = 2 * s + (lane >> 4);
            int ch = (((m_loc & 1) << 2) + kc) ^ ((m_loc >> 1) & 7);
            ldA[s] = (uint32_t)((m_loc >> 1) * 128 + ch * 16);
        }
    }
    uint32_t ldB[2];
    {
        int k_low = ((lane >> 4)) * 8 + (lane & 7);
        int nc = (wn >> 3) + ((lane >> 3) & 1);
        #pragma unroll
        for (int s = 0; s < 2; s++) {
            int k_loc = 16 * s + k_low;
            ldB[s] = (uint32_t)(k_loc * 256 + ((nc ^ (k_loc & 7)) * 16));
        }
    }

    float acc[4][4][4];
    #pragma unroll
    for (int mt = 0; mt < 4; mt++)
        #pragma unroll
        for (int nt = 0; nt < 4; nt++)
            #pragma unroll
            for (int i = 0; i < 4; i++) acc[mt][nt][i] = 0.f;

    const int nk = K / TBK;
    float4 ra[2][2], rb[2][2];

    #pragma unroll
    for (int j = 0; j < 2; j++) {
        ra[j][0] = *(const float4*)(Arow + j * 8);
        ra[j][1] = *(const float4*)(Arow + j * 8 + 4);
        rb[j][0] = *(const float4*)(Brow + j * 64);
        rb[j][1] = *(const float4*)(Brow + j * 64 + 4);
    }
    #pragma unroll
    for (int j = 0; j < 2; j++) {
        *(uint4*)(smA + stsA[j]) = make_uint4(
            pack2(ra[j][0].x, ra[j][0].y), pack2(ra[j][0].z, ra[j][0].w),
            pack2(ra[j][1].x, ra[j][1].y), pack2(ra[j][1].z, ra[j][1].w));
        *(uint4*)(smB + stsB[j]) = make_uint4(
            pack2(rb[j][0].x, rb[j][0].y), pack2(rb[j][0].z, rb[j][0].w),
            pack2(rb[j][1].x, rb[j][1].y), pack2(rb[j][1].z, rb[j][1].w));
    }
    __syncthreads();

    int buf = 0;
    for (int c = 0; c < nk; c++) {
        if (c + 1 < nk) {
            const float* Ap = Arow + (size_t)(c + 1) * TBK;
            const float* Bp = Brow + (size_t)(c + 1) * TBK * N;
            #pragma unroll
            for (int j = 0; j < 2; j++) {
                ra[j][0] = *(const float4*)(Ap + j * 8);
                ra[j][1] = *(const float4*)(Ap + j * 8 + 4);
                rb[j][0] = *(const float4*)(Bp + j * 64);
                rb[j][1] = *(const float4*)(Bp + j * 64 + 4);
            }
        }

        const uint32_t aoff = uA + buf * A_STAGE;
        const uint32_t boff = uB + buf * B_STAGE;
        #pragma unroll
        for (int s = 0; s < 2; s++) {
            unsigned af[4][4];
            #pragma unroll
            for (int mt = 0; mt < 4; mt++)
                LDSM_X4(af[mt][0], af[mt][1], af[mt][2], af[mt][3],
                        aoff + ldA[s] + mt * 1024);
            unsigned bf[4][2];
            #pragma unroll
            for (int ng = 0; ng < 2; ng++) {
                unsigned r0, r1, r2, r3;
                LDSM_X4_T(r0, r1, r2, r3, (boff + ldB[s]) ^ (ng * 32));
                bf[2 * ng + 0][0] = r0; bf[2 * ng + 0][1] = r2;
                bf[2 * ng + 1][0] = r1; bf[2 * ng + 1][1] = r3;
            }
            #pragma unroll
            for (int mt = 0; mt < 4; mt++)
                #pragma unroll
                for (int nt = 0; nt < 4; nt++)
                    mma_f16(acc[mt][nt], af[mt], bf[nt]);
        }

        if (c + 1 < nk) {
            char* dA = smA + (buf ^ 1) * A_STAGE;
            char* dB = smB + (buf ^ 1) * B_STAGE;
            #pragma unroll
            for (int j = 0; j < 2; j++) {
                *(uint4*)(dA + stsA[j]) = make_uint4(
                    pack2(ra[j][0].x, ra[j][0].y), pack2(ra[j][0].z, ra[j][0].w),
                    pack2(ra[j][1].x, ra[j][1].y), pack2(ra[j][1].z, ra[j][1].w));
                *(uint4*)(dB + stsB[j]) = make_uint4(
                    pack2(rb[j][0].x, rb[j][0].y), pack2(rb[j][0].z, rb[j][0].w),
                    pack2(rb[j][1].x, rb[j][1].y), pack2(rb[j][1].z, rb[j][1].w));
            }
            __syncthreads();
        }
        buf ^= 1;
    }

    const int lr = lane >> 2, lc = lane & 3;
    #pragma unroll
    for (int mt = 0; mt < 4; mt++) {
        #pragma unroll
        for (int nt = 0; nt < 4; nt++) {
            int gr = rowBase + wm + mt * 16 + lr;
            int gc = colBase + wn + nt * 8 + 2 * lc;
            *(float2*)&C[(size_t)gr * N + gc] =
                make_float2(acc[mt][nt][0], acc[mt][nt][1]);
            *(float2*)&C[(size_t)(gr + 8) * N + gc] =
                make_float2(acc[mt][nt][2], acc[mt][nt][3]);
        }
    }
}

// ================= RoPE for Q/K (fp16 out) =================
// qkv columns: [0:4096)=q, [4096:8192)=v, [8192:12288)=k
__global__ void rope_qk_kernel(
    const float* __restrict__ qkv, const int* __restrict__ pos_ids,
    __half* __restrict__ Q, __half* __restrict__ K)
{
    size_t p = (size_t)blockIdx.x * blockDim.x + threadIdx.x;
    int row = (int)(p >> 12);
    int rem = (int)(p & 4095);
    int isk = rem >> 11;
    int f   = (rem & 2047) * 2;
    int col = isk ? (8192 + f) : f;
    int b = row >> 11, s = row & 2047;
    int hh = f >> 8, d = f & 255;

    float2 x = *(const float2*)&qkv[(size_t)row * F3H + col];
    float2 y = x;
    if (d < 64) {
        float inv = expf(-(float)d * (9.210340371976184f / 64.f));
        float fr = (float)pos_ids[row] * inv;
        float c, sn;
        sincosf(fr, &sn, &c);
        y.x = x.x * c - x.y * sn;
        y.y = x.y * c + x.x * sn;
    }
    size_t dst = ((size_t)((b * NHc + hh) * Sc + s)) * HDc + d;
    __half2 h = __floats2half2_rn(y.x, y.y);
    if (isk) *(__half2*)&K[dst] = h;
    else     *(__half2*)&Q[dst] = h;
}

// ================= V convert (fp32 qkv section -> fp16 [bh][s][d]) =================
__global__ void vconv_kernel(const float* __restrict__ qkv, __half* __restrict__ V)
{
    size_t idx = (size_t)blockIdx.x * blockDim.x + threadIdx.x;  // 8 elems each
    size_t e = idx * 8;
    int d = (int)(e & 255);
    int s = (int)((e >> 8) & 2047);
    int bh = (int)(e >> 19);
    int b = bh >> 4, h = bh & 15;
    const float* src = &qkv[(size_t)(b * Sc + s) * F3H + Hc + h * HDc + d];
    float4 a = *(const float4*)src;
    float4 c = *(const float4*)(src + 4);
    *(uint4*)&V[e] = make_uint4(pack2(a.x, a.y), pack2(a.z, a.w),
                                pack2(c.x, c.y), pack2(c.z, c.w));
}

// ================= fp16 flash attention =================
// CTA: 64 q-rows, BN=64 k per iter, 8 warps (4 m-groups x 2 n-groups)
#define ATT3_SMEM 108032

__global__ __launch_bounds__(256, 2) void attn3_kernel(
    const __half* __restrict__ Qh, const __half* __restrict__ Kh,
    const __half* __restrict__ Vh, float* __restrict__ O)
{
    extern __shared__ char smc[];
    char* Qs = smc;                 // 64 x 512B (swizzled)
    char* Ks = smc + 32768;         // 64 x 512B
    char* Vs = smc + 65536;         // 64 x 512B
    char* Ph = smc + 98304;         // 64 x 128B (swizzled)
    float* wmax = (float*)(smc + 106496);  // [2][64]
    float* wsum = wmax + 128;              // [2][64]
    float* m_s  = wsum + 128;              // [64]
    float* l_s  = m_s + 64;                // [64]

    const uint32_t uQ = smem_u32(Qs), uK = smem_u32(Ks);
    const uint32_t uV = smem_u32(Vs), uP = smem_u32(Ph);

    const int tid = threadIdx.x, lane = tid & 31, wid = tid >> 5;
    const int lr = lane >> 2, lc = lane & 3;
    const int wm = (wid & 3) * 16;
    const int nw = wid >> 2;            // 0 or 1
    const int wnq = nw * 32;            // QK col offset
    const int wnp = nw * 128;           // PV col offset
    const int qt = blockIdx.x, hh = blockIdx.y, b = blockIdx.z;
    const int q0 = qt * 64;
    const size_t bh = (size_t)(b * NHc + hh);

    const __half* Qg = Qh + bh * Sc * HDc;
    const __half* Kg = Kh + bh * Sc * HDc;
    const __half* Vg = Vh + bh * Sc * HDc;

    // staging geometry: 64 rows x 32 chunks of 16B
    const int srow = tid >> 2;
    const int sc0  = (tid & 3) * 8;

    // stage Q (once)
    #pragma unroll
    for (int j = 0; j < 8; j++) {
        int c = sc0 + j;
        uint4 v = *(const uint4*)(Qg + (size_t)(q0 + srow) * HDc + c * 8);
        *(uint4*)(Qs + srow * 512 + ((c ^ (srow & 7)) * 16)) = v;
    }
    if (tid < 64) { m_s[tid] = -1e30f; l_s[tid] = 0.f; }

    float o[16][4];
    #pragma unroll
    for (int nt = 0; nt < 16; nt++)
        #pragma unroll
        for (int i = 0; i < 4; i++) o[nt][i] = 0.f;

    // fragment geometry
    const int rowa = (lane & 7) + ((lane >> 3) & 1) * 8;   // row within 16-group
    const int arow = wm + rowa;
    const uint32_t aQbase = uQ + arow * 512;
    const uint32_t aPbase = uP + arow * 128;
    const int a_sw = arow & 7;
    const int r0l = wm + lr, r1l = wm + lr + 8;            // local row ids

    for (int kt = 0; kt <= qt; kt++) {
        __syncthreads();
        const int k0 = kt * 64;

        // stage K, V tiles (64 x 256 halfs each)
        #pragma unroll
        for (int j = 0; j < 8; j++) {
            int c = sc0 + j;
            uint4 v = *(const uint4*)(Kg + (size_t)(k0 + srow) * HDc + c * 8);
            *(uint4*)(Ks + srow * 512 + ((c ^ (srow & 7)) * 16)) = v;
        }
        #pragma unroll
        for (int j = 0; j < 8; j++) {
            int c = sc0 + j;
            uint4 v = *(const uint4*)(Vg + (size_t)(k0 + srow) * HDc + c * 8);
            *(uint4*)(Vs + srow * 512 + ((c ^ (srow & 7)) * 16)) = v;
        }
        __syncthreads();

        // ---- S = Q K^T (per warp 16 x 32) ----
        float sacc[4][4];
        #pragma unroll
        for (int nt = 0; nt < 4; nt++)
            #pragma unroll
            for (int i = 0; i < 4; i++) sacc[nt][i] = 0.f;

        #pragma unroll
        for (int j = 0; j < 16; j++) {
            const int kc = 2 * j + (lane >> 4);
            unsigned a0, a1, a2, a3;
            LDSM_X4(a0, a1, a2, a3, aQbase + ((kc ^ a_sw) * 16));
            unsigned af[4] = {a0, a1, a2, a3};
            #pragma unroll
            for (int g = 0; g < 2; g++) {
                const int nrow = wnq + g * 16 + rowa;
                unsigned r0, r1, r2, r3;
                LDSM_X4(r0, r1, r2, r3, uK + nrow * 512 + ((kc ^ (nrow & 7)) * 16));
                unsigned b0[2] = {r0, r2}, b1[2] = {r1, r3};
                mma_f16(sacc[2 * g + 0], af, b0);
                mma_f16(sacc[2 * g + 1], af, b1);
            }
        }

        // scale + causal mask (registers)
        {
            const bool diag = (kt == qt);
            const int qg0 = q0 + r0l, qg1 = q0 + r1l;
            #pragma unroll
            for (int nt = 0; nt < 4; nt++) {
                const int cg = k0 + wnq + nt * 8 + 2 * lc;
                sacc[nt][0] *= 0.0625f; sacc[nt][1] *= 0.0625f;
                sacc[nt][2] *= 0.0625f; sacc[nt][3] *= 0.0625f;
                if (diag) {
                    if (cg     > qg0) sacc[nt][0] = -1e30f;
                    if (cg + 1 > qg0) sacc[nt][1] = -1e30f;
                    if (cg     > qg1) sacc[nt][2] = -1e30f;
                    if (cg + 1 > qg1) sacc[nt][3] = -1e30f;
                }
            }
        }

        // ---- warp-partial row max ----
        float mx0 = -1e30f, mx1 = -1e30f;
        #pragma unroll
        for (int nt = 0; nt < 4; nt++) {
            mx0 = fmaxf(mx0, fmaxf(sacc[nt][0], sacc[nt][1]));
            mx1 = fmaxf(mx1, fmaxf(sacc[nt][2], sacc[nt][3]));
        }
        mx0 = fmaxf(mx0, __shfl_xor_sync(0xffffffffu, mx0, 1));
        mx0 = fmaxf(mx0, __shfl_xor_sync(0xffffffffu, mx0, 2));
        mx1 = fmaxf(mx1, __shfl_xor_sync(0xffffffffu, mx1, 1));
        mx1 = fmaxf(mx1, __shfl_xor_sync(0xffffffffu, mx1, 2));
        if (lc == 0) {
            wmax[nw * 64 + r0l] = mx0;
            wmax[nw * 64 + r1l] = mx1;
        }
        __syncthreads();

        // ---- combine, exp, pack P, partial sums ----
        const float mold0 = m_s[r0l], mold1 = m_s[r1l];
        const float mn0 = fmaxf(mold0, fmaxf(wmax[r0l], wmax[64 + r0l]));
        const float mn1 = fmaxf(mold1, fmaxf(wmax[r1l], wmax[64 + r1l]));
        const float al0 = __expf(mold0 - mn0);
        const float al1 = __expf(mold1 - mn1);

        float s0 = 0.f, s1 = 0.f;
        #pragma unroll
        for (int nt = 0; nt < 4; nt++) {
            float p00 = __expf(sacc[nt][0] - mn0);
            float p01 = __expf(sacc[nt][1] - mn0);
            float p10 = __expf(sacc[nt][2] - mn1);
            float p11 = __expf(sacc[nt][3] - mn1);
            s0 += p00 + p01; s1 += p10 + p11;
            const int col = wnq + nt * 8 + 2 * lc;
            const int cch = col >> 3;
            const int cin = (col & 7) * 2;
            *(unsigned*)(Ph + r0l * 128 + ((cch ^ (r0l & 7)) * 16) + cin) = pack2(p00, p01);
            *(unsigned*)(Ph + r1l * 128 + ((cch ^ (r1l & 7)) * 16) + cin) = pack2(p10, p11);
        }
        s0 += __shfl_xor_sync(0xffffffffu, s0, 1);
        s0 += __shfl_xor_sync(0xffffffffu, s0, 2);
        s1 += __shfl_xor_sync(0xffffffffu, s1, 1);
        s1 += __shfl_xor_sync(0xffffffffu, s1, 2);
        if (lc == 0) {
            wsum[nw * 64 + r0l] = s0;
            wsum[nw * 64 + r1l] = s1;
        }
        __syncthreads();

        // stats update (single writer per row)
        if (nw == 0 && lc == 0) {
            l_s[r0l] = l_s[r0l] * al0 + wsum[r0l] + wsum[64 + r0l];
            l_s[r1l] = l_s[r1l] * al1 + wsum[r1l] + wsum[64 + r1l];
            m_s[r0l] = mn0;
            m_s[r1l] = mn1;
        }

        // rescale O
        #pragma unroll
        for (int nt = 0; nt < 16; nt++) {
            o[nt][0] *= al0; o[nt][1] *= al0;
            o[nt][2] *= al1; o[nt][3] *= al1;
        }

        // ---- O += P V (per warp 16 x 128) ----
        #pragma unroll
        for (int j = 0; j < 4; j++) {
            const int kc = 2 * j + (lane >> 4);
            unsigned a0, a1, a2, a3;
            LDSM_X4(a0, a1, a2, a3, aPbase + ((kc ^ (arow & 7)) * 16));
            unsigned af[4] = {a0, a1, a2, a3};
            const int k_loc = 16 * j + ((lane >> 4)) * 8 + (lane & 7);
            #pragma unroll
            for (int ng = 0; ng < 8; ng++) {
                const int nc = (wnp >> 3) + 2 * ng + ((lane >> 3) & 1);
                unsigned r0, r1, r2, r3;
                LDSM_X4_T(r0, r1, r2, r3,
                          uV + k_loc * 512 + ((nc ^ (k_loc & 7)) * 16));
                unsigned b0[2] = {r0, r2}, b1[2] = {r1, r3};
                mma_f16(o[2 * ng + 0], af, b0);
                mma_f16(o[2 * ng + 1], af, b1);
            }
        }
    }

    __syncthreads();
    // epilogue: normalize + write [B*S][H]
    {
        const float i0 = 1.f / l_s[r0l];
        const float i1 = 1.f / l_s[r1l];
        #pragma unroll
        for (int nt = 0; nt < 16; nt++) {
            const int col = hh * HDc + wnp + nt * 8 + 2 * lc;
            size_t base0 = ((size_t)(b * Sc + q0 + r0l)) * Hc + col;
            size_t base1 = ((size_t)(b * Sc + q0 + r1l)) * Hc + col;
            *(float2*)&O[base0] = make_float2(o[nt][0] * i0, o[nt][1] * i0);
            *(float2*)&O[base1] = make_float2(o[nt][2] * i1, o[nt][3] * i1);
        }
    }
}

// ================= launch =================
extern "C" void kernel_launch(void* const* d_in, const int* in_sizes, int n_in,
                              void* d_out, int out_size)
{
    const float* hidden = (const float*)d_in[0];
    const int*   pos    = (const int*)d_in[1];
    const float* w_qkv  = (const float*)d_in[2];
    const float* w_out  = (const float*)d_in[3];
    float* out = (float*)d_out;

    float *qkv, *attn;
    __half *Qh, *Kh, *Vh;
    cudaGetSymbolAddress((void**)&qkv,  g_qkv);
    cudaGetSymbolAddress((void**)&attn, g_attn);
    cudaGetSymbolAddress((void**)&Qh,   g_Qh);
    cudaGetSymbolAddress((void**)&Kh,   g_Kh);
    cudaGetSymbolAddress((void**)&Vh,   g_Vh);

    cudaFuncSetAttribute(attn3_kernel,
                         cudaFuncAttributeMaxDynamicSharedMemorySize, ATT3_SMEM);

    // 1) qkv = hidden @ w_qkv (fp16 mma)
    f16_gemm_kernel<<<(4096 / TBM) * (F3H / TBN), 256>>>(
        hidden, w_qkv, qkv, F3H, 4096, F3H / TBN);

    // 2) RoPE -> Qh, Kh (fp16); V convert -> Vh (fp16)
    rope_qk_kernel<<<65536, 256>>>(qkv, pos, Qh, Kh);
    vconv_kernel<<<8192, 256>>>(qkv, Vh);

    // 3) fp16 flash attention -> attn [B*S][H]
    attn3_kernel<<<dim3(Sc / 64, NHc, Bc), 256, ATT3_SMEM>>>(Qh, Kh, Vh, attn);

    // 4) out = attn @ w_out (fp16 mma)
    f16_gemm_kernel<<<(4096 / TBM) * (Hc / TBN), 256>>>(
        attn, w_out, out, Hc, 4096, Hc / TBN);
}

// round 7
// speedup vs baseline: 4.3744x; 1.1997x over previous
#include <cuda_runtime.h>
#include <cuda_fp16.h>
#include <math.h>
#include <stdint.h>

// Problem constants
#define Bc 2
#define Sc 2048
#define Hc 4096
#define NHc 16
#define HDc 256
#define F3H 12288   // 3*H

// ---------------- scratch ----------------
__device__ __half g_hidh[(size_t)4096 * 4096];     // hidden fp16
__device__ __half g_wqkvh[(size_t)4096 * 12288];   // w_qkv fp16
__device__ __half g_wouth[(size_t)4096 * 4096];    // w_out fp16
__device__ __half g_qkvh[(size_t)4096 * 12288];    // qkv fp16 [B*S][3H]
__device__ __half g_Qh[(size_t)32 * 2048 * 256];   // [B*NH][S][HD]
__device__ __half g_Kh[(size_t)32 * 2048 * 256];
__device__ __half g_Vh[(size_t)32 * 2048 * 256];
__device__ __half g_attnh[(size_t)4096 * 4096];    // attn out fp16 [B*S][H]

// ---------------- helpers ----------------
__device__ __forceinline__ uint32_t smem_u32(const void* p) {
    uint32_t a;
    asm("{ .reg .u64 t; cvta.to.shared.u64 t, %1; cvt.u32.u64 %0, t; }"
        : "=r"(a) : "l"(p));
    return a;
}
__device__ __forceinline__ unsigned pack2(float x, float y) {
    __half2 h = __floats2half2_rn(x, y);
    return *(unsigned*)&h;
}
__device__ __forceinline__ void mma_f16(float* d, const unsigned* a, const unsigned* b) {
    asm volatile(
        "mma.sync.aligned.m16n8k16.row.col.f32.f16.f16.f32 "
        "{%0,%1,%2,%3}, {%4,%5,%6,%7}, {%8,%9}, {%0,%1,%2,%3};\n"
        : "+f"(d[0]), "+f"(d[1]), "+f"(d[2]), "+f"(d[3])
        : "r"(a[0]), "r"(a[1]), "r"(a[2]), "r"(a[3]), "r"(b[0]), "r"(b[1]));
}
#define LDSM_X4(r0, r1, r2, r3, addr) \
    asm volatile("ldmatrix.sync.aligned.m8n8.x4.shared.b16 {%0,%1,%2,%3}, [%4];" \
        : "=r"(r0), "=r"(r1), "=r"(r2), "=r"(r3) : "r"(addr))
#define LDSM_X4_T(r0, r1, r2, r3, addr) \
    asm volatile("ldmatrix.sync.aligned.m8n8.x4.trans.shared.b16 {%0,%1,%2,%3}, [%4];" \
        : "=r"(r0), "=r"(r1), "=r"(r2), "=r"(r3) : "r"(addr))
#define CP16(saddr, gptr) \
    asm volatile("cp.async.cg.shared.global [%0], [%1], 16;" \
        :: "r"(saddr), "l"(gptr) : "memory")
#define CP_COMMIT() asm volatile("cp.async.commit_group;" ::: "memory")
#define CP_WAIT2()  asm volatile("cp.async.wait_group 2;" ::: "memory")

// ================= fp32 -> fp16 convert =================
__global__ void f2h_kernel(const float* __restrict__ s, __half* __restrict__ d, int n8)
{
    int i = blockIdx.x * blockDim.x + threadIdx.x;
    if (i >= n8) return;
    size_t e = (size_t)i * 8;
    float4 a = *(const float4*)&s[e];
    float4 c = *(const float4*)&s[e + 4];
    *(uint4*)&d[e] = make_uint4(pack2(a.x, a.y), pack2(a.z, a.w),
                                pack2(c.x, c.y), pack2(c.z, c.w));
}

// ================= fp16 GEMM, cp.async 4-stage =================
// C[MxN] = A[MxK] * B[KxN]; A,B fp16 row-major; C fp16 or fp32.
// tile 128x128x32, 8 warps (2x4 of 64x32)
#define TBM 128
#define TBN 128
#define TBK 32
#define NS 4
#define A_ST 8192
#define B_ST 8192
#define ST_BYTES (A_ST + B_ST)
#define GEMM_SMEM (NS * ST_BYTES)   // 65536

template <int OUT_HALF>
__global__ __launch_bounds__(256, 2) void f16_gemm_cp(
    const __half* __restrict__ A, const __half* __restrict__ B,
    void* __restrict__ Cv, int N, int K, int colTiles)
{
    extern __shared__ char sm[];
    const uint32_t uS = smem_u32(sm);

    const int tid  = threadIdx.x;
    const int lane = tid & 31;
    const int wid  = tid >> 5;
    const int wm   = (wid & 1) * 64;
    const int wn   = (wid >> 1) * 32;

    // supertile rasterization (8 row-tiles per group)
    const int bid = blockIdx.x;
    const int per = 8 * colTiles;
    const int rem = bid % per;
    const int rt = (bid / per) * 8 + (rem & 7);
    const int ct = rem >> 3;
    const int rowBase = rt * TBM;
    const int colBase = ct * TBN;

    // staging geometry (cp.async, 16B chunks)
    const int am   = tid >> 1;            // A row 0..127
    const int akc0 = (tid & 1) * 2;       // A chunk base
    uint32_t stA[2];
    #pragma unroll
    for (int j = 0; j < 2; j++) {
        int kc = akc0 + j;
        int ch = (((am & 1) << 2) + kc) ^ ((am >> 1) & 7);
        stA[j] = (uint32_t)((am >> 1) * 128 + ch * 16);
    }
    const int bk  = tid >> 3;             // B row 0..31
    const int bn0 = tid & 7;              // B chunk base
    uint32_t stB[2];
    #pragma unroll
    for (int j = 0; j < 2; j++) {
        int nc = bn0 + 8 * j;
        stB[j] = (uint32_t)(bk * 256 + (nc ^ (bk & 7)) * 16);
    }
    const __half* Ag = A + (size_t)(rowBase + am) * K + akc0 * 8;
    const __half* Bg = B + (size_t)bk * N + colBase + bn0 * 8;

    // fragment geometry
    uint32_t ldA[2];
    {
        int m_loc = wm + ((lane >> 3) & 1) * 8 + (lane & 7);
        #pragma unroll
        for (int s = 0; s < 2; s++) {
            int kc = 2 * s + (lane >> 4);
            int ch = (((m_loc & 1) << 2) + kc) ^ ((m_loc >> 1) & 7);
            ldA[s] = (uint32_t)((m_loc >> 1) * 128 + ch * 16);
        }
    }
    uint32_t ldB[2];
    {
        int k_low = (lane >> 4) * 8 + (lane & 7);
        int nc = (wn >> 3) + ((lane >> 3) & 1);
        #pragma unroll
        for (int s = 0; s < 2; s++) {
            int k_loc = 16 * s + k_low;
            ldB[s] = (uint32_t)(k_loc * 256 + ((nc ^ (k_loc & 7)) * 16));
        }
    }

    float acc[4][4][4];
    #pragma unroll
    for (int mt = 0; mt < 4; mt++)
        #pragma unroll
        for (int nt = 0; nt < 4; nt++)
            #pragma unroll
            for (int i = 0; i < 4; i++) acc[mt][nt][i] = 0.f;

    const int nk = K / TBK;

    // prologue: stages 0..NS-2
    #pragma unroll
    for (int c = 0; c < NS - 1; c++) {
        uint32_t base = uS + (c & 3) * ST_BYTES;
        const __half* Ap = Ag + (size_t)c * TBK;
        const __half* Bp = Bg + (size_t)c * TBK * N;
        CP16(base + stA[0], Ap);
        CP16(base + stA[1], Ap + 8);
        CP16(base + A_ST + stB[0], Bp);
        CP16(base + A_ST + stB[1], Bp + 64);
        CP_COMMIT();
    }

    for (int c = 0; c < nk; c++) {
        CP_WAIT2();
        __syncthreads();

        const uint32_t aoff = uS + (c & 3) * ST_BYTES;
        const uint32_t boff = aoff + A_ST;
        #pragma unroll
        for (int s = 0; s < 2; s++) {
            unsigned af[4][4];
            #pragma unroll
            for (int mt = 0; mt < 4; mt++)
                LDSM_X4(af[mt][0], af[mt][1], af[mt][2], af[mt][3],
                        aoff + ldA[s] + mt * 1024);
            unsigned bf[4][2];
            #pragma unroll
            for (int ng = 0; ng < 2; ng++) {
                unsigned r0, r1, r2, r3;
                LDSM_X4_T(r0, r1, r2, r3, (boff + ldB[s]) ^ (ng * 32));
                bf[2 * ng + 0][0] = r0; bf[2 * ng + 0][1] = r2;
                bf[2 * ng + 1][0] = r1; bf[2 * ng + 1][1] = r3;
            }
            #pragma unroll
            for (int mt = 0; mt < 4; mt++)
                #pragma unroll
                for (int nt = 0; nt < 4; nt++)
                    mma_f16(acc[mt][nt], af[mt], bf[nt]);
        }

        const int cn = c + NS - 1;
        if (cn < nk) {
            uint32_t base = uS + (cn & 3) * ST_BYTES;
            const __half* Ap = Ag + (size_t)cn * TBK;
            const __half* Bp = Bg + (size_t)cn * TBK * N;
            CP16(base + stA[0], Ap);
            CP16(base + stA[1], Ap + 8);
            CP16(base + A_ST + stB[0], Bp);
            CP16(base + A_ST + stB[1], Bp + 64);
        }
        CP_COMMIT();
    }

    // epilogue
    const int lr = lane >> 2, lc = lane & 3;
    #pragma unroll
    for (int mt = 0; mt < 4; mt++) {
        #pragma unroll
        for (int nt = 0; nt < 4; nt++) {
            int gr = rowBase + wm + mt * 16 + lr;
            int gc = colBase + wn + nt * 8 + 2 * lc;
            if (OUT_HALF) {
                __half* C = (__half*)Cv;
                *(unsigned*)&C[(size_t)gr * N + gc] =
                    pack2(acc[mt][nt][0], acc[mt][nt][1]);
                *(unsigned*)&C[(size_t)(gr + 8) * N + gc] =
                    pack2(acc[mt][nt][2], acc[mt][nt][3]);
            } else {
                float* C = (float*)Cv;
                *(float2*)&C[(size_t)gr * N + gc] =
                    make_float2(acc[mt][nt][0], acc[mt][nt][1]);
                *(float2*)&C[(size_t)(gr + 8) * N + gc] =
                    make_float2(acc[mt][nt][2], acc[mt][nt][3]);
            }
        }
    }
}

// ================= RoPE for Q/K (fp16 in/out) =================
// qkv columns: [0:4096)=q, [4096:8192)=v, [8192:12288)=k
__global__ void rope_qk_kernel(
    const __half* __restrict__ qkv, const int* __restrict__ pos_ids,
    __half* __restrict__ Q, __half* __restrict__ K)
{
    size_t p = (size_t)blockIdx.x * blockDim.x + threadIdx.x;
    int row = (int)(p >> 12);
    int rem = (int)(p & 4095);
    int isk = rem >> 11;
    int f   = (rem & 2047) * 2;
    int col = isk ? (8192 + f) : f;
    int b = row >> 11, s = row & 2047;
    int hh = f >> 8, d = f & 255;

    float2 x = __half22float2(*(const __half2*)&qkv[(size_t)row * F3H + col]);
    float2 y = x;
    if (d < 64) {
        float inv = expf(-(float)d * (9.210340371976184f / 64.f));
        float fr = (float)pos_ids[row] * inv;
        float c, sn;
        sincosf(fr, &sn, &c);
        y.x = x.x * c - x.y * sn;
        y.y = x.y * c + x.x * sn;
    }
    size_t dst = ((size_t)((b * NHc + hh) * Sc + s)) * HDc + d;
    __half2 h = __floats2half2_rn(y.x, y.y);
    if (isk) *(__half2*)&K[dst] = h;
    else     *(__half2*)&Q[dst] = h;
}

// ================= V reshape (fp16 qkv v-section -> [bh][s][d]) =================
__global__ void vconv_kernel(const __half* __restrict__ qkv, __half* __restrict__ V)
{
    size_t idx = (size_t)blockIdx.x * blockDim.x + threadIdx.x;  // 8 halfs each
    size_t e = idx * 8;
    int d = (int)(e & 255);
    int s = (int)((e >> 8) & 2047);
    int bh = (int)(e >> 19);
    int b = bh >> 4, h = bh & 15;
    const __half* src = &qkv[(size_t)(b * Sc + s) * F3H + Hc + h * HDc + d];
    *(uint4*)&V[e] = *(const uint4*)src;
}

// ================= fp16 flash attention (out: fp16) =================
#define ATT3_SMEM 108032

__global__ __launch_bounds__(256, 2) void attn3_kernel(
    const __half* __restrict__ Qh, const __half* __restrict__ Kh,
    const __half* __restrict__ Vh, __half* __restrict__ O)
{
    extern __shared__ char smc[];
    char* Qs = smc;                 // 64 x 512B (swizzled)
    char* Ks = smc + 32768;
    char* Vs = smc + 65536;
    char* Ph = smc + 98304;         // 64 x 128B (swizzled)
    float* wmax = (float*)(smc + 106496);  // [2][64]
    float* wsum = wmax + 128;              // [2][64]
    float* m_s  = wsum + 128;              // [64]
    float* l_s  = m_s + 64;                // [64]

    const uint32_t uQ = smem_u32(Qs), uK = smem_u32(Ks);
    const uint32_t uV = smem_u32(Vs), uP = smem_u32(Ph);

    const int tid = threadIdx.x, lane = tid & 31, wid = tid >> 5;
    const int lr = lane >> 2, lc = lane & 3;
    const int wm = (wid & 3) * 16;
    const int nw = wid >> 2;
    const int wnq = nw * 32;
    const int wnp = nw * 128;
    const int qt = blockIdx.x, hh = blockIdx.y, b = blockIdx.z;
    const int q0 = qt * 64;
    const size_t bh = (size_t)(b * NHc + hh);

    const __half* Qg = Qh + bh * Sc * HDc;
    const __half* Kg = Kh + bh * Sc * HDc;
    const __half* Vg = Vh + bh * Sc * HDc;

    const int srow = tid >> 2;
    const int sc0  = (tid & 3) * 8;

    #pragma unroll
    for (int j = 0; j < 8; j++) {
        int c = sc0 + j;
        uint4 v = *(const uint4*)(Qg + (size_t)(q0 + srow) * HDc + c * 8);
        *(uint4*)(Qs + srow * 512 + ((c ^ (srow & 7)) * 16)) = v;
    }
    if (tid < 64) { m_s[tid] = -1e30f; l_s[tid] = 0.f; }

    float o[16][4];
    #pragma unroll
    for (int nt = 0; nt < 16; nt++)
        #pragma unroll
        for (int i = 0; i < 4; i++) o[nt][i] = 0.f;

    const int rowa = (lane & 7) + ((lane >> 3) & 1) * 8;
    const int arow = wm + rowa;
    const uint32_t aQbase = uQ + arow * 512;
    const uint32_t aPbase = uP + arow * 128;
    const int a_sw = arow & 7;
    const int r0l = wm + lr, r1l = wm + lr + 8;

    for (int kt = 0; kt <= qt; kt++) {
        __syncthreads();
        const int k0 = kt * 64;

        #pragma unroll
        for (int j = 0; j < 8; j++) {
            int c = sc0 + j;
            uint4 v = *(const uint4*)(Kg + (size_t)(k0 + srow) * HDc + c * 8);
            *(uint4*)(Ks + srow * 512 + ((c ^ (srow & 7)) * 16)) = v;
        }
        #pragma unroll
        for (int j = 0; j < 8; j++) {
            int c = sc0 + j;
            uint4 v = *(const uint4*)(Vg + (size_t)(k0 + srow) * HDc + c * 8);
            *(uint4*)(Vs + srow * 512 + ((c ^ (srow & 7)) * 16)) = v;
        }
        __syncthreads();

        float sacc[4][4];
        #pragma unroll
        for (int nt = 0; nt < 4; nt++)
            #pragma unroll
            for (int i = 0; i < 4; i++) sacc[nt][i] = 0.f;

        #pragma unroll
        for (int j = 0; j < 16; j++) {
            const int kc = 2 * j + (lane >> 4);
            unsigned a0, a1, a2, a3;
            LDSM_X4(a0, a1, a2, a3, aQbase + ((kc ^ a_sw) * 16));
            unsigned af[4] = {a0, a1, a2, a3};
            #pragma unroll
            for (int g = 0; g < 2; g++) {
                const int nrow = wnq + g * 16 + rowa;
                unsigned r0, r1, r2, r3;
                LDSM_X4(r0, r1, r2, r3, uK + nrow * 512 + ((kc ^ (nrow & 7)) * 16));
                unsigned b0[2] = {r0, r2}, b1[2] = {r1, r3};
                mma_f16(sacc[2 * g + 0], af, b0);
                mma_f16(sacc[2 * g + 1], af, b1);
            }
        }

        {
            const bool diag = (kt == qt);
            const int qg0 = q0 + r0l, qg1 = q0 + r1l;
            #pragma unroll
            for (int nt = 0; nt < 4; nt++) {
                const int cg = k0 + wnq + nt * 8 + 2 * lc;
                sacc[nt][0] *= 0.0625f; sacc[nt][1] *= 0.0625f;
                sacc[nt][2] *= 0.0625f; sacc[nt][3] *= 0.0625f;
                if (diag) {
                    if (cg     > qg0) sacc[nt][0] = -1e30f;
                    if (cg + 1 > qg0) sacc[nt][1] = -1e30f;
                    if (cg     > qg1) sacc[nt][2] = -1e30f;
                    if (cg + 1 > qg1) sacc[nt][3] = -1e30f;
                }
            }
        }

        float mx0 = -1e30f, mx1 = -1e30f;
        #pragma unroll
        for (int nt = 0; nt < 4; nt++) {
            mx0 = fmaxf(mx0, fmaxf(sacc[nt][0], sacc[nt][1]));
            mx1 = fmaxf(mx1, fmaxf(sacc[nt][2], sacc[nt][3]));
        }
        mx0 = fmaxf(mx0, __shfl_xor_sync(0xffffffffu, mx0, 1));
        mx0 = fmaxf(mx0, __shfl_xor_sync(0xffffffffu, mx0, 2));
        mx1 = fmaxf(mx1, __shfl_xor_sync(0xffffffffu, mx1, 1));
        mx1 = fmaxf(mx1, __shfl_xor_sync(0xffffffffu, mx1, 2));
        if (lc == 0) {
            wmax[nw * 64 + r0l] = mx0;
            wmax[nw * 64 + r1l] = mx1;
        }
        __syncthreads();

        const float mold0 = m_s[r0l], mold1 = m_s[r1l];
        const float mn0 = fmaxf(mold0, fmaxf(wmax[r0l], wmax[64 + r0l]));
        const float mn1 = fmaxf(mold1, fmaxf(wmax[r1l], wmax[64 + r1l]));
        const float al0 = __expf(mold0 - mn0);
        const float al1 = __expf(mold1 - mn1);

        float s0 = 0.f, s1 = 0.f;
        #pragma unroll
        for (int nt = 0; nt < 4; nt++) {
            float p00 = __expf(sacc[nt][0] - mn0);
            float p01 = __expf(sacc[nt][1] - mn0);
            float p10 = __expf(sacc[nt][2] - mn1);
            float p11 = __expf(sacc[nt][3] - mn1);
            s0 += p00 + p01; s1 += p10 + p11;
            const int col = wnq + nt * 8 + 2 * lc;
            const int cch = col >> 3;
            const int cin = (col & 7) * 2;
            *(unsigned*)(Ph + r0l * 128 + ((cch ^ (r0l & 7)) * 16) + cin) = pack2(p00, p01);
            *(unsigned*)(Ph + r1l * 128 + ((cch ^ (r1l & 7)) * 16) + cin) = pack2(p10, p11);
        }
        s0 += __shfl_xor_sync(0xffffffffu, s0, 1);
        s0 += __shfl_xor_sync(0xffffffffu, s0, 2);
        s1 += __shfl_xor_sync(0xffffffffu, s1, 1);
        s1 += __shfl_xor_sync(0xffffffffu, s1, 2);
        if (lc == 0) {
            wsum[nw * 64 + r0l] = s0;
            wsum[nw * 64 + r1l] = s1;
        }
        __syncthreads();

        if (nw == 0 && lc == 0) {
            l_s[r0l] = l_s[r0l] * al0 + wsum[r0l] + wsum[64 + r0l];
            l_s[r1l] = l_s[r1l] * al1 + wsum[r1l] + wsum[64 + r1l];
            m_s[r0l] = mn0;
            m_s[r1l] = mn1;
        }

        #pragma unroll
        for (int nt = 0; nt < 16; nt++) {
            o[nt][0] *= al0; o[nt][1] *= al0;
            o[nt][2] *= al1; o[nt][3] *= al1;
        }

        #pragma unroll
        for (int j = 0; j < 4; j++) {
            const int kc = 2 * j + (lane >> 4);
            unsigned a0, a1, a2, a3;
            LDSM_X4(a0, a1, a2, a3, aPbase + ((kc ^ (arow & 7)) * 16));
            unsigned af[4] = {a0, a1, a2, a3};
            const int k_loc = 16 * j + (lane >> 4) * 8 + (lane & 7);
            #pragma unroll
            for (int ng = 0; ng < 8; ng++) {
                const int nc = (wnp >> 3) + 2 * ng + ((lane >> 3) & 1);
                unsigned r0, r1, r2, r3;
                LDSM_X4_T(r0, r1, r2, r3,
                          uV + k_loc * 512 + ((nc ^ (k_loc & 7)) * 16));
                unsigned b0[2] = {r0, r2}, b1[2] = {r1, r3};
                mma_f16(o[2 * ng + 0], af, b0);
                mma_f16(o[2 * ng + 1], af, b1);
            }
        }
    }

    __syncthreads();
    {
        const float i0 = 1.f / l_s[r0l];
        const float i1 = 1.f / l_s[r1l];
        #pragma unroll
        for (int nt = 0; nt < 16; nt++) {
            const int col = hh * HDc + wnp + nt * 8 + 2 * lc;
            size_t base0 = ((size_t)(b * Sc + q0 + r0l)) * Hc + col;
            size_t base1 = ((size_t)(b * Sc + q0 + r1l)) * Hc + col;
            *(unsigned*)&O[base0] = pack2(o[nt][0] * i0, o[nt][1] * i0);
            *(unsigned*)&O[base1] = pack2(o[nt][2] * i1, o[nt][3] * i1);
        }
    }
}

// ================= launch =================
extern "C" void kernel_launch(void* const* d_in, const int* in_sizes, int n_in,
                              void* d_out, int out_size)
{
    const float* hidden = (const float*)d_in[0];
    const int*   pos    = (const int*)d_in[1];
    const float* w_qkv  = (const float*)d_in[2];
    const float* w_out  = (const float*)d_in[3];
    float* out = (float*)d_out;

    __half *hidh, *wqkvh, *wouth, *qkvh, *Qh, *Kh, *Vh, *attnh;
    cudaGetSymbolAddress((void**)&hidh,  g_hidh);
    cudaGetSymbolAddress((void**)&wqkvh, g_wqkvh);
    cudaGetSymbolAddress((void**)&wouth, g_wouth);
    cudaGetSymbolAddress((void**)&qkvh,  g_qkvh);
    cudaGetSymbolAddress((void**)&Qh,    g_Qh);
    cudaGetSymbolAddress((void**)&Kh,    g_Kh);
    cudaGetSymbolAddress((void**)&Vh,    g_Vh);
    cudaGetSymbolAddress((void**)&attnh, g_attnh);

    cudaFuncSetAttribute(f16_gemm_cp<0>,
                         cudaFuncAttributeMaxDynamicSharedMemorySize, GEMM_SMEM);
    cudaFuncSetAttribute(f16_gemm_cp<1>,
                         cudaFuncAttributeMaxDynamicSharedMemorySize, GEMM_SMEM);
    cudaFuncSetAttribute(attn3_kernel,
                         cudaFuncAttributeMaxDynamicSharedMemorySize, ATT3_SMEM);

    // 0) fp32 -> fp16 conversions
    f2h_kernel<<<8192, 256>>>(hidden, hidh, 2097152);
    f2h_kernel<<<24576, 256>>>(w_qkv, wqkvh, 6291456);
    f2h_kernel<<<8192, 256>>>(w_out, wouth, 2097152);

    // 1) qkv = hidden @ w_qkv  (fp16 out)
    f16_gemm_cp<1><<<(4096 / TBM) * (F3H / TBN), 256, GEMM_SMEM>>>(
        hidh, wqkvh, qkvh, F3H, 4096, F3H / TBN);

    // 2) RoPE -> Qh, Kh ; V reshape -> Vh
    rope_qk_kernel<<<65536, 256>>>(qkvh, pos, Qh, Kh);
    vconv_kernel<<<8192, 256>>>(qkvh, Vh);

    // 3) fp16 flash attention -> attnh (fp16)
    attn3_kernel<<<dim3(Sc / 64, NHc, Bc), 256, ATT3_SMEM>>>(Qh, Kh, Vh, attnh);

    // 4) out = attn @ w_out  (fp32 out)
    f16_gemm_cp<0><<<(4096 / TBM) * (Hc / TBN), 256, GEMM_SMEM>>>(
        attnh, wouth, out, Hc, 4096, Hc / TBN);
}

// round 8
// speedup vs baseline: 6.8758x; 1.5718x over previous
#include <cuda_runtime.h>
#include <cuda_fp16.h>
#include <math.h>
#include <stdint.h>

// Problem constants
#define Bc 2
#define Sc 2048
#define Hc 4096
#define NHc 16
#define HDc 256
#define F3H 12288   // 3*H

// ---------------- scratch ----------------
__device__ __half g_hidh[(size_t)4096 * 4096];     // hidden fp16
__device__ __half g_wqkvh[(size_t)4096 * 12288];   // w_qkv fp16
__device__ __half g_wouth[(size_t)4096 * 4096];    // w_out fp16
__device__ __half g_qkvh[(size_t)4096 * 12288];    // qkv fp16 [B*S][3H]
__device__ __half g_Qh[(size_t)32 * 2048 * 256];   // [B*NH][S][HD]
__device__ __half g_Kh[(size_t)32 * 2048 * 256];
__device__ __half g_Vh[(size_t)32 * 2048 * 256];
__device__ __half g_attnh[(size_t)4096 * 4096];    // attn out fp16 [B*S][H]

// ---------------- helpers ----------------
__device__ __forceinline__ uint32_t smem_u32(const void* p) {
    uint32_t a;
    asm("{ .reg .u64 t; cvta.to.shared.u64 t, %1; cvt.u32.u64 %0, t; }"
        : "=r"(a) : "l"(p));
    return a;
}
__device__ __forceinline__ unsigned pack2(float x, float y) {
    __half2 h = __floats2half2_rn(x, y);
    return *(unsigned*)&h;
}
__device__ __forceinline__ void mma_f16(float* d, const unsigned* a, const unsigned* b) {
    asm volatile(
        "mma.sync.aligned.m16n8k16.row.col.f32.f16.f16.f32 "
        "{%0,%1,%2,%3}, {%4,%5,%6,%7}, {%8,%9}, {%0,%1,%2,%3};\n"
        : "+f"(d[0]), "+f"(d[1]), "+f"(d[2]), "+f"(d[3])
        : "r"(a[0]), "r"(a[1]), "r"(a[2]), "r"(a[3]), "r"(b[0]), "r"(b[1]));
}
#define LDSM_X4(r0, r1, r2, r3, addr) \
    asm volatile("ldmatrix.sync.aligned.m8n8.x4.shared.b16 {%0,%1,%2,%3}, [%4];" \
        : "=r"(r0), "=r"(r1), "=r"(r2), "=r"(r3) : "r"(addr))
#define LDSM_X4_T(r0, r1, r2, r3, addr) \
    asm volatile("ldmatrix.sync.aligned.m8n8.x4.trans.shared.b16 {%0,%1,%2,%3}, [%4];" \
        : "=r"(r0), "=r"(r1), "=r"(r2), "=r"(r3) : "r"(addr))
#define CP16(saddr, gptr) \
    asm volatile("cp.async.cg.shared.global [%0], [%1], 16;" \
        :: "r"(saddr), "l"(gptr) : "memory")
#define CP_COMMIT() asm volatile("cp.async.commit_group;" ::: "memory")
#define CP_WAIT2()  asm volatile("cp.async.wait_group 2;" ::: "memory")
#define CP_WAIT0()  asm volatile("cp.async.wait_group 0;" ::: "memory")

// ================= fp32 -> fp16 convert =================
__global__ void f2h_kernel(const float* __restrict__ s, __half* __restrict__ d, int n8)
{
    int i = blockIdx.x * blockDim.x + threadIdx.x;
    if (i >= n8) return;
    size_t e = (size_t)i * 8;
    float4 a = *(const float4*)&s[e];
    float4 c = *(const float4*)&s[e + 4];
    *(uint4*)&d[e] = make_uint4(pack2(a.x, a.y), pack2(a.z, a.w),
                                pack2(c.x, c.y), pack2(c.z, c.w));
}

// ================= fp16 GEMM, cp.async 4-stage, 128x256 tile =================
// C[MxN] = A[MxK] * B[KxN]; A,B fp16 row-major; 8 warps, warp tile 64x64.
#define TBM 128
#define TBN 256
#define TBK 32
#define NS 4
#define A_ST 8192                     // 128 rows x 32k x 2B (64 pair-rows x 128B)
#define B_ST 16384                    // 32 k x 256 n x 2B (rows of 512B)
#define ST_BYTES (A_ST + B_ST)        // 24576
#define GEMM_SMEM (NS * ST_BYTES)     // 98304

template <int OUT_HALF>
__global__ __launch_bounds__(256, 1) void f16_gemm_cp(
    const __half* __restrict__ A, const __half* __restrict__ B,
    void* __restrict__ Cv, int N, int K, int colTiles)
{
    extern __shared__ char sm[];
    const uint32_t uS = smem_u32(sm);

    const int tid  = threadIdx.x;
    const int lane = tid & 31;
    const int wid  = tid >> 5;
    const int wm   = (wid & 1) * 64;
    const int wn   = (wid >> 1) * 64;

    // supertile rasterization (8 row-tiles per group)
    const int bid = blockIdx.x;
    const int per = 8 * colTiles;
    const int rem = bid % per;
    const int rt = (bid / per) * 8 + (rem & 7);
    const int ct = rem >> 3;
    const int rowBase = rt * TBM;
    const int colBase = ct * TBN;

    // ---- staging geometry (cp.async 16B) ----
    const int am   = tid >> 1;            // A row 0..127
    const int akc0 = (tid & 1) * 2;       // A chunk base
    uint32_t stA[2];
    #pragma unroll
    for (int j = 0; j < 2; j++) {
        int kc = akc0 + j;
        int ch = (((am & 1) << 2) + kc) ^ ((am >> 1) & 7);
        stA[j] = (uint32_t)((am >> 1) * 128 + ch * 16);
    }
    const int bk  = tid >> 3;             // B row 0..31
    const int bn0 = tid & 7;              // B chunk base
    uint32_t stB[4];
    #pragma unroll
    for (int j = 0; j < 4; j++) {
        int nc = bn0 + 8 * j;
        stB[j] = (uint32_t)(bk * 512 + ((nc ^ (bk & 7)) * 16));
    }
    const __half* Ag = A + (size_t)(rowBase + am) * K + akc0 * 8;
    const __half* Bg = B + (size_t)bk * N + colBase + bn0 * 8;

    // ---- fragment geometry ----
    uint32_t ldA[2];
    {
        int m_loc = wm + ((lane >> 3) & 1) * 8 + (lane & 7);
        #pragma unroll
        for (int s = 0; s < 2; s++) {
            int kc = 2 * s + (lane >> 4);
            int ch = (((m_loc & 1) << 2) + kc) ^ ((m_loc >> 1) & 7);
            ldA[s] = (uint32_t)((m_loc >> 1) * 128 + ch * 16);
        }
    }
    uint32_t ldBt[2][4];
    {
        const int ncb = (wn >> 3) + ((lane >> 3) & 1);
        #pragma unroll
        for (int s = 0; s < 2; s++) {
            int k_loc = 16 * s + (lane >> 4) * 8 + (lane & 7);
            #pragma unroll
            for (int ng = 0; ng < 4; ng++) {
                int nc = ncb + 2 * ng;
                ldBt[s][ng] = (uint32_t)(k_loc * 512 + ((nc ^ (k_loc & 7)) * 16));
            }
        }
    }

    float acc[4][8][4];
    #pragma unroll
    for (int mt = 0; mt < 4; mt++)
        #pragma unroll
        for (int nt = 0; nt < 8; nt++)
            #pragma unroll
            for (int i = 0; i < 4; i++) acc[mt][nt][i] = 0.f;

    const int nk = K / TBK;

    // prologue: stages 0..NS-2
    #pragma unroll
    for (int c = 0; c < NS - 1; c++) {
        uint32_t base = uS + (c & 3) * ST_BYTES;
        const __half* Ap = Ag + (size_t)c * TBK;
        const __half* Bp = Bg + (size_t)c * TBK * N;
        CP16(base + stA[0], Ap);
        CP16(base + stA[1], Ap + 8);
        #pragma unroll
        for (int j = 0; j < 4; j++)
            CP16(base + A_ST + stB[j], Bp + 64 * j);
        CP_COMMIT();
    }

    for (int c = 0; c < nk; c++) {
        CP_WAIT2();
        __syncthreads();

        const uint32_t aoff = uS + (c & 3) * ST_BYTES;
        const uint32_t boff = aoff + A_ST;
        #pragma unroll
        for (int s = 0; s < 2; s++) {
            unsigned af[4][4];
            #pragma unroll
            for (int mt = 0; mt < 4; mt++)
                LDSM_X4(af[mt][0], af[mt][1], af[mt][2], af[mt][3],
                        aoff + ldA[s] + mt * 1024);
            unsigned bf[8][2];
            #pragma unroll
            for (int ng = 0; ng < 4; ng++) {
                unsigned r0, r1, r2, r3;
                LDSM_X4_T(r0, r1, r2, r3, boff + ldBt[s][ng]);
                bf[2 * ng + 0][0] = r0; bf[2 * ng + 0][1] = r2;
                bf[2 * ng + 1][0] = r1; bf[2 * ng + 1][1] = r3;
            }
            #pragma unroll
            for (int mt = 0; mt < 4; mt++)
                #pragma unroll
                for (int nt = 0; nt < 8; nt++)
                    mma_f16(acc[mt][nt], af[mt], bf[nt]);
        }

        const int cn = c + NS - 1;
        if (cn < nk) {
            uint32_t base = uS + (cn & 3) * ST_BYTES;
            const __half* Ap = Ag + (size_t)cn * TBK;
            const __half* Bp = Bg + (size_t)cn * TBK * N;
            CP16(base + stA[0], Ap);
            CP16(base + stA[1], Ap + 8);
            #pragma unroll
            for (int j = 0; j < 4; j++)
                CP16(base + A_ST + stB[j], Bp + 64 * j);
        }
        CP_COMMIT();
    }

    // epilogue
    const int lr = lane >> 2, lc = lane & 3;
    #pragma unroll
    for (int mt = 0; mt < 4; mt++) {
        #pragma unroll
        for (int nt = 0; nt < 8; nt++) {
            int gr = rowBase + wm + mt * 16 + lr;
            int gc = colBase + wn + nt * 8 + 2 * lc;
            if (OUT_HALF) {
                __half* C = (__half*)Cv;
                *(unsigned*)&C[(size_t)gr * N + gc] =
                    pack2(acc[mt][nt][0], acc[mt][nt][1]);
                *(unsigned*)&C[(size_t)(gr + 8) * N + gc] =
                    pack2(acc[mt][nt][2], acc[mt][nt][3]);
            } else {
                float* C = (float*)Cv;
                *(float2*)&C[(size_t)gr * N + gc] =
                    make_float2(acc[mt][nt][0], acc[mt][nt][1]);
                *(float2*)&C[(size_t)(gr + 8) * N + gc] =
                    make_float2(acc[mt][nt][2], acc[mt][nt][3]);
            }
        }
    }
}

// ================= RoPE for Q/K (fp16 in/out) =================
// qkv columns: [0:4096)=q, [4096:8192)=v, [8192:12288)=k
__global__ void rope_qk_kernel(
    const __half* __restrict__ qkv, const int* __restrict__ pos_ids,
    __half* __restrict__ Q, __half* __restrict__ K)
{
    size_t p = (size_t)blockIdx.x * blockDim.x + threadIdx.x;
    int row = (int)(p >> 12);
    int rem = (int)(p & 4095);
    int isk = rem >> 11;
    int f   = (rem & 2047) * 2;
    int col = isk ? (8192 + f) : f;
    int b = row >> 11, s = row & 2047;
    int hh = f >> 8, d = f & 255;

    float2 x = __half22float2(*(const __half2*)&qkv[(size_t)row * F3H + col]);
    float2 y = x;
    if (d < 64) {
        float inv = expf(-(float)d * (9.210340371976184f / 64.f));
        float fr = (float)pos_ids[row] * inv;
        float c, sn;
        sincosf(fr, &sn, &c);
        y.x = x.x * c - x.y * sn;
        y.y = x.y * c + x.x * sn;
    }
    size_t dst = ((size_t)((b * NHc + hh) * Sc + s)) * HDc + d;
    __half2 h = __floats2half2_rn(y.x, y.y);
    if (isk) *(__half2*)&K[dst] = h;
    else     *(__half2*)&Q[dst] = h;
}

// ================= V reshape (fp16 qkv v-section -> [bh][s][d]) =================
__global__ void vconv_kernel(const __half* __restrict__ qkv, __half* __restrict__ V)
{
    size_t idx = (size_t)blockIdx.x * blockDim.x + threadIdx.x;  // 8 halfs each
    size_t e = idx * 8;
    int d = (int)(e & 255);
    int s = (int)((e >> 8) & 2047);
    int bh = (int)(e >> 19);
    int b = bh >> 4, h = bh & 15;
    const __half* src = &qkv[(size_t)(b * Sc + s) * F3H + Hc + h * HDc + d];
    *(uint4*)&V[e] = *(const uint4*)src;
}

// ================= fp16 flash attention, cp.async double-buffered K/V =================
// smem: Q 32K | K[2] 64K | V[2] 64K | P 8K | stats
#define AQ_OFF 0
#define AK_OFF 32768
#define AV_OFF 98304
#define AP_OFF 163840
#define AST_OFF 172032
#define ATT4_SMEM 173600

__global__ __launch_bounds__(256, 1) void attn4_kernel(
    const __half* __restrict__ Qh, const __half* __restrict__ Kh,
    const __half* __restrict__ Vh, __half* __restrict__ O)
{
    extern __shared__ char smc[];
    char* Qs = smc + AQ_OFF;
    char* Ph = smc + AP_OFF;
    float* wmax = (float*)(smc + AST_OFF);  // [2][64]
    float* wsum = wmax + 128;               // [2][64]
    float* m_s  = wsum + 128;               // [64]
    float* l_s  = m_s + 64;                 // [64]

    const uint32_t uBase = smem_u32(smc);
    const uint32_t uQ = uBase + AQ_OFF;
    const uint32_t uK = uBase + AK_OFF;
    const uint32_t uV = uBase + AV_OFF;
    const uint32_t uP = uBase + AP_OFF;

    const int tid = threadIdx.x, lane = tid & 31, wid = tid >> 5;
    const int lr = lane >> 2, lc = lane & 3;
    const int wm = (wid & 3) * 16;
    const int nw = wid >> 2;
    const int wnq = nw * 32;
    const int wnp = nw * 128;
    const int qt = blockIdx.x, hh = blockIdx.y, b = blockIdx.z;
    const int q0 = qt * 64;
    const size_t bh = (size_t)(b * NHc + hh);

    const __half* Qg = Qh + bh * Sc * HDc;
    const __half* Kg = Kh + bh * Sc * HDc;
    const __half* Vg = Vh + bh * Sc * HDc;

    const int srow = tid >> 2;
    const int sc0  = (tid & 3) * 8;
    uint32_t stKV[8];
    #pragma unroll
    for (int j = 0; j < 8; j++) {
        int c = sc0 + j;
        stKV[j] = (uint32_t)(srow * 512 + ((c ^ (srow & 7)) * 16));
    }

    // stage Q (plain stores; covered by first loop-top sync)
    #pragma unroll
    for (int j = 0; j < 8; j++) {
        int c = sc0 + j;
        uint4 v = *(const uint4*)(Qg + (size_t)(q0 + srow) * HDc + c * 8);
        *(uint4*)(Qs + srow * 512 + ((c ^ (srow & 7)) * 16)) = v;
    }
    if (tid < 64) { m_s[tid] = -1e30f; l_s[tid] = 0.f; }

    float o[16][4];
    #pragma unroll
    for (int nt = 0; nt < 16; nt++)
        #pragma unroll
        for (int i = 0; i < 4; i++) o[nt][i] = 0.f;

    const int rowa = (lane & 7) + ((lane >> 3) & 1) * 8;
    const int arow = wm + rowa;
    const uint32_t aQbase = uQ + arow * 512;
    const uint32_t aPbase = uP + arow * 128;
    const int a_sw = arow & 7;
    const int r0l = wm + lr, r1l = wm + lr + 8;

    // prologue: prefetch tile 0 into buf 0
    {
        const __half* Kp = Kg + (size_t)srow * HDc + sc0 * 8;
        const __half* Vp = Vg + (size_t)srow * HDc + sc0 * 8;
        #pragma unroll
        for (int j = 0; j < 8; j++) {
            CP16(uK + stKV[j], Kp + j * 8);
            CP16(uV + stKV[j], Vp + j * 8);
        }
        CP_COMMIT();
    }

    for (int kt = 0; kt <= qt; kt++) {
        const int buf = kt & 1;
        const uint32_t uKb = uK + buf * 32768;
        const uint32_t uVb = uV + buf * 32768;

        CP_WAIT0();
        __syncthreads();   // K/V(kt) visible to all; all warps done with buf^1

        // prefetch K/V(kt+1) into buf^1 (overlaps with entire iteration)
        if (kt < qt) {
            const int kn = (kt + 1) * 64;
            const __half* Kp = Kg + (size_t)(kn + srow) * HDc + sc0 * 8;
            const __half* Vp = Vg + (size_t)(kn + srow) * HDc + sc0 * 8;
            const uint32_t uKn = uK + (buf ^ 1) * 32768;
            const uint32_t uVn = uV + (buf ^ 1) * 32768;
            #pragma unroll
            for (int j = 0; j < 8; j++) {
                CP16(uKn + stKV[j], Kp + j * 8);
                CP16(uVn + stKV[j], Vp + j * 8);
            }
        }
        CP_COMMIT();

        const int k0 = kt * 64;

        // ---- S = Q K^T ----
        float sacc[4][4];
        #pragma unroll
        for (int nt = 0; nt < 4; nt++)
            #pragma unroll
            for (int i = 0; i < 4; i++) sacc[nt][i] = 0.f;

        #pragma unroll
        for (int j = 0; j < 16; j++) {
            const int kc = 2 * j + (lane >> 4);
            unsigned a0, a1, a2, a3;
            LDSM_X4(a0, a1, a2, a3, aQbase + ((kc ^ a_sw) * 16));
            unsigned af[4] = {a0, a1, a2, a3};
            #pragma unroll
            for (int g = 0; g < 2; g++) {
                const int nrow = wnq + g * 16 + rowa;
                unsigned r0, r1, r2, r3;
                LDSM_X4(r0, r1, r2, r3, uKb + nrow * 512 + ((kc ^ (nrow & 7)) * 16));
                unsigned b0[2] = {r0, r2}, b1[2] = {r1, r3};
                mma_f16(sacc[2 * g + 0], af, b0);
                mma_f16(sacc[2 * g + 1], af, b1);
            }
        }

        // scale + causal mask
        {
            const bool diag = (kt == qt);
            const int qg0 = q0 + r0l, qg1 = q0 + r1l;
            #pragma unroll
            for (int nt = 0; nt < 4; nt++) {
                const int cg = k0 + wnq + nt * 8 + 2 * lc;
                sacc[nt][0] *= 0.0625f; sacc[nt][1] *= 0.0625f;
                sacc[nt][2] *= 0.0625f; sacc[nt][3] *= 0.0625f;
                if (diag) {
                    if (cg     > qg0) sacc[nt][0] = -1e30f;
                    if (cg + 1 > qg0) sacc[nt][1] = -1e30f;
                    if (cg     > qg1) sacc[nt][2] = -1e30f;
                    if (cg + 1 > qg1) sacc[nt][3] = -1e30f;
                }
            }
        }

        // warp-partial row max
        float mx0 = -1e30f, mx1 = -1e30f;
        #pragma unroll
        for (int nt = 0; nt < 4; nt++) {
            mx0 = fmaxf(mx0, fmaxf(sacc[nt][0], sacc[nt][1]));
            mx1 = fmaxf(mx1, fmaxf(sacc[nt][2], sacc[nt][3]));
        }
        mx0 = fmaxf(mx0, __shfl_xor_sync(0xffffffffu, mx0, 1));
        mx0 = fmaxf(mx0, __shfl_xor_sync(0xffffffffu, mx0, 2));
        mx1 = fmaxf(mx1, __shfl_xor_sync(0xffffffffu, mx1, 1));
        mx1 = fmaxf(mx1, __shfl_xor_sync(0xffffffffu, mx1, 2));
        if (lc == 0) {
            wmax[nw * 64 + r0l] = mx0;
            wmax[nw * 64 + r1l] = mx1;
        }
        __syncthreads();

        const float mold0 = m_s[r0l], mold1 = m_s[r1l];
        const float mn0 = fmaxf(mold0, fmaxf(wmax[r0l], wmax[64 + r0l]));
        const float mn1 = fmaxf(mold1, fmaxf(wmax[r1l], wmax[64 + r1l]));
        const float al0 = __expf(mold0 - mn0);
        const float al1 = __expf(mold1 - mn1);

        float s0 = 0.f, s1 = 0.f;
        #pragma unroll
        for (int nt = 0; nt < 4; nt++) {
            float p00 = __expf(sacc[nt][0] - mn0);
            float p01 = __expf(sacc[nt][1] - mn0);
            float p10 = __expf(sacc[nt][2] - mn1);
            float p11 = __expf(sacc[nt][3] - mn1);
            s0 += p00 + p01; s1 += p10 + p11;
            const int col = wnq + nt * 8 + 2 * lc;
            const int cch = col >> 3;
            const int cin = (col & 7) * 2;
            *(unsigned*)(Ph + r0l * 128 + ((cch ^ (r0l & 7)) * 16) + cin) = pack2(p00, p01);
            *(unsigned*)(Ph + r1l * 128 + ((cch ^ (r1l & 7)) * 16) + cin) = pack2(p10, p11);
        }
        s0 += __shfl_xor_sync(0xffffffffu, s0, 1);
        s0 += __shfl_xor_sync(0xffffffffu, s0, 2);
        s1 += __shfl_xor_sync(0xffffffffu, s1, 1);
        s1 += __shfl_xor_sync(0xffffffffu, s1, 2);
        if (lc == 0) {
            wsum[nw * 64 + r0l] = s0;
            wsum[nw * 64 + r1l] = s1;
        }
        __syncthreads();

        if (nw == 0 && lc == 0) {
            l_s[r0l] = l_s[r0l] * al0 + wsum[r0l] + wsum[64 + r0l];
            l_s[r1l] = l_s[r1l] * al1 + wsum[r1l] + wsum[64 + r1l];
            m_s[r0l] = mn0;
            m_s[r1l] = mn1;
        }

        #pragma unroll
        for (int nt = 0; nt < 16; nt++) {
            o[nt][0] *= al0; o[nt][1] *= al0;
            o[nt][2] *= al1; o[nt][3] *= al1;
        }

        // ---- O += P V ----
        #pragma unroll
        for (int j = 0; j < 4; j++) {
            const int kc = 2 * j + (lane >> 4);
            unsigned a0, a1, a2, a3;
            LDSM_X4(a0, a1, a2, a3, aPbase + ((kc ^ (arow & 7)) * 16));
            unsigned af[4] = {a0, a1, a2, a3};
            const int k_loc = 16 * j + (lane >> 4) * 8 + (lane & 7);
            #pragma unroll
            for (int ng = 0; ng < 8; ng++) {
                const int nc = (wnp >> 3) + 2 * ng + ((lane >> 3) & 1);
                unsigned r0, r1, r2, r3;
                LDSM_X4_T(r0, r1, r2, r3,
                          uVb + k_loc * 512 + ((nc ^ (k_loc & 7)) * 16));
                unsigned b0[2] = {r0, r2}, b1[2] = {r1, r3};
                mma_f16(o[2 * ng + 0], af, b0);
                mma_f16(o[2 * ng + 1], af, b1);
            }
        }
    }

    __syncthreads();
    {
        const float i0 = 1.f / l_s[r0l];
        const float i1 = 1.f / l_s[r1l];
        #pragma unroll
        for (int nt = 0; nt < 16; nt++) {
            const int col = hh * HDc + wnp + nt * 8 + 2 * lc;
            size_t base0 = ((size_t)(b * Sc + q0 + r0l)) * Hc + col;
            size_t base1 = ((size_t)(b * Sc + q0 + r1l)) * Hc + col;
            *(unsigned*)&O[base0] = pack2(o[nt][0] * i0, o[nt][1] * i0);
            *(unsigned*)&O[base1] = pack2(o[nt][2] * i1, o[nt][3] * i1);
        }
    }
}

// ================= launch =================
extern "C" void kernel_launch(void* const* d_in, const int* in_sizes, int n_in,
                              void* d_out, int out_size)
{
    const float* hidden = (const float*)d_in[0];
    const int*   pos    = (const int*)d_in[1];
    const float* w_qkv  = (const float*)d_in[2];
    const float* w_out  = (const float*)d_in[3];
    float* out = (float*)d_out;

    __half *hidh, *wqkvh, *wouth, *qkvh, *Qh, *Kh, *Vh, *attnh;
    cudaGetSymbolAddress((void**)&hidh,  g_hidh);
    cudaGetSymbolAddress((void**)&wqkvh, g_wqkvh);
    cudaGetSymbolAddress((void**)&wouth, g_wouth);
    cudaGetSymbolAddress((void**)&qkvh,  g_qkvh);
    cudaGetSymbolAddress((void**)&Qh,    g_Qh);
    cudaGetSymbolAddress((void**)&Kh,    g_Kh);
    cudaGetSymbolAddress((void**)&Vh,    g_Vh);
    cudaGetSymbolAddress((void**)&attnh, g_attnh);

    cudaFuncSetAttribute(f16_gemm_cp<0>,
                         cudaFuncAttributeMaxDynamicSharedMemorySize, GEMM_SMEM);
    cudaFuncSetAttribute(f16_gemm_cp<1>,
                         cudaFuncAttributeMaxDynamicSharedMemorySize, GEMM_SMEM);
    cudaFuncSetAttribute(attn4_kernel,
                         cudaFuncAttributeMaxDynamicSharedMemorySize, ATT4_SMEM);

    // 0) fp32 -> fp16 conversions
    f2h_kernel<<<8192, 256>>>(hidden, hidh, 2097152);
    f2h_kernel<<<24576, 256>>>(w_qkv, wqkvh, 6291456);
    f2h_kernel<<<8192, 256>>>(w_out, wouth, 2097152);

    // 1) qkv = hidden @ w_qkv  (fp16 out)
    f16_gemm_cp<1><<<(4096 / TBM) * (F3H / TBN), 256, GEMM_SMEM>>>(
        hidh, wqkvh, qkvh, F3H, 4096, F3H / TBN);

    // 2) RoPE -> Qh, Kh ; V reshape -> Vh
    rope_qk_kernel<<<65536, 256>>>(qkvh, pos, Qh, Kh);
    vconv_kernel<<<8192, 256>>>(qkvh, Vh);

    // 3) fp16 flash attention (cp.async) -> attnh (fp16)
    attn4_kernel<<<dim3(Sc / 64, NHc, Bc), 256, ATT4_SMEM>>>(Qh, Kh, Vh, attnh);

    // 4) out = attn @ w_out  (fp32 out)
    f16_gemm_cp<0><<<(4096 / TBM) * (Hc / TBN), 256, GEMM_SMEM>>>(
        attnh, wouth, out, Hc, 4096, Hc / TBN);
}

// round 9
// speedup vs baseline: 7.1666x; 1.0423x over previous
#include <cuda_runtime.h>
#include <cuda_fp16.h>
#include <math.h>
#include <stdint.h>

// Problem constants
#define Bc 2
#define Sc 2048
#define Hc 4096
#define NHc 16
#define HDc 256
#define F3H 12288   // 3*H

// ---------------- scratch ----------------
__device__ __half g_hidh[(size_t)4096 * 4096];     // hidden fp16
__device__ __half g_wqkvh[(size_t)4096 * 12288];   // w_qkv fp16
__device__ __half g_wouth[(size_t)4096 * 4096];    // w_out fp16
__device__ __half g_qkvh[(size_t)4096 * 12288];    // qkv fp16 [B*S][3H]
__device__ __half g_Qh[(size_t)32 * 2048 * 256];   // [B*NH][S][HD]
__device__ __half g_Kh[(size_t)32 * 2048 * 256];
__device__ __half g_Vh[(size_t)32 * 2048 * 256];
__device__ __half g_attnh[(size_t)4096 * 4096];    // attn out fp16 [B*S][H]

// ---------------- helpers ----------------
__device__ __forceinline__ uint32_t smem_u32(const void* p) {
    uint32_t a;
    asm("{ .reg .u64 t; cvta.to.shared.u64 t, %1; cvt.u32.u64 %0, t; }"
        : "=r"(a) : "l"(p));
    return a;
}
__device__ __forceinline__ unsigned pack2(float x, float y) {
    __half2 h = __floats2half2_rn(x, y);
    return *(unsigned*)&h;
}
__device__ __forceinline__ void mma_f16(float* d, const unsigned* a, const unsigned* b) {
    asm volatile(
        "mma.sync.aligned.m16n8k16.row.col.f32.f16.f16.f32 "
        "{%0,%1,%2,%3}, {%4,%5,%6,%7}, {%8,%9}, {%0,%1,%2,%3};\n"
        : "+f"(d[0]), "+f"(d[1]), "+f"(d[2]), "+f"(d[3])
        : "r"(a[0]), "r"(a[1]), "r"(a[2]), "r"(a[3]), "r"(b[0]), "r"(b[1]));
}
#define LDSM_X4(r0, r1, r2, r3, addr) \
    asm volatile("ldmatrix.sync.aligned.m8n8.x4.shared.b16 {%0,%1,%2,%3}, [%4];" \
        : "=r"(r0), "=r"(r1), "=r"(r2), "=r"(r3) : "r"(addr))
#define LDSM_X4_T(r0, r1, r2, r3, addr) \
    asm volatile("ldmatrix.sync.aligned.m8n8.x4.trans.shared.b16 {%0,%1,%2,%3}, [%4];" \
        : "=r"(r0), "=r"(r1), "=r"(r2), "=r"(r3) : "r"(addr))
#define CP16(saddr, gptr) \
    asm volatile("cp.async.cg.shared.global [%0], [%1], 16;" \
        :: "r"(saddr), "l"(gptr) : "memory")
#define CP_COMMIT() asm volatile("cp.async.commit_group;" ::: "memory")
#define CP_WAIT2()  asm volatile("cp.async.wait_group 2;" ::: "memory")
#define CP_WAIT0()  asm volatile("cp.async.wait_group 0;" ::: "memory")

// ================= fp32 -> fp16 convert =================
__global__ void f2h_kernel(const float* __restrict__ s, __half* __restrict__ d, int n8)
{
    int i = blockIdx.x * blockDim.x + threadIdx.x;
    if (i >= n8) return;
    size_t e = (size_t)i * 8;
    float4 a = *(const float4*)&s[e];
    float4 c = *(const float4*)&s[e + 4];
    *(uint4*)&d[e] = make_uint4(pack2(a.x, a.y), pack2(a.z, a.w),
                                pack2(c.x, c.y), pack2(c.z, c.w));
}

// ================= fp16 GEMM, cp.async 4-stage, 128x256 tile (R8, unchanged) =================
#define TBM 128
#define TBN 256
#define TBK 32
#define NS 4
#define A_ST 8192
#define B_ST 16384
#define ST_BYTES (A_ST + B_ST)
#define GEMM_SMEM (NS * ST_BYTES)   // 98304

template <int OUT_HALF>
__global__ __launch_bounds__(256, 1) void f16_gemm_cp(
    const __half* __restrict__ A, const __half* __restrict__ B,
    void* __restrict__ Cv, int N, int K, int colTiles)
{
    extern __shared__ char sm[];
    const uint32_t uS = smem_u32(sm);

    const int tid  = threadIdx.x;
    const int lane = tid & 31;
    const int wid  = tid >> 5;
    const int wm   = (wid & 1) * 64;
    const int wn   = (wid >> 1) * 64;

    const int bid = blockIdx.x;
    const int per = 8 * colTiles;
    const int rem = bid % per;
    const int rt = (bid / per) * 8 + (rem & 7);
    const int ct = rem >> 3;
    const int rowBase = rt * TBM;
    const int colBase = ct * TBN;

    const int am   = tid >> 1;
    const int akc0 = (tid & 1) * 2;
    uint32_t stA[2];
    #pragma unroll
    for (int j = 0; j < 2; j++) {
        int kc = akc0 + j;
        int ch = (((am & 1) << 2) + kc) ^ ((am >> 1) & 7);
        stA[j] = (uint32_t)((am >> 1) * 128 + ch * 16);
    }
    const int bk  = tid >> 3;
    const int bn0 = tid & 7;
    uint32_t stB[4];
    #pragma unroll
    for (int j = 0; j < 4; j++) {
        int nc = bn0 + 8 * j;
        stB[j] = (uint32_t)(bk * 512 + ((nc ^ (bk & 7)) * 16));
    }
    const __half* Ag = A + (size_t)(rowBase + am) * K + akc0 * 8;
    const __half* Bg = B + (size_t)bk * N + colBase + bn0 * 8;

    uint32_t ldA[2];
    {
        int m_loc = wm + ((lane >> 3) & 1) * 8 + (lane & 7);
        #pragma unroll
        for (int s = 0; s < 2; s++) {
            int kc = 2 * s + (lane >> 4);
            int ch = (((m_loc & 1) << 2) + kc) ^ ((m_loc >> 1) & 7);
            ldA[s] = (uint32_t)((m_loc >> 1) * 128 + ch * 16);
        }
    }
    uint32_t ldBt[2][4];
    {
        const int ncb = (wn >> 3) + ((lane >> 3) & 1);
        #pragma unroll
        for (int s = 0; s < 2; s++) {
            int k_loc = 16 * s + (lane >> 4) * 8 + (lane & 7);
            #pragma unroll
            for (int ng = 0; ng < 4; ng++) {
                int nc = ncb + 2 * ng;
                ldBt[s][ng] = (uint32_t)(k_loc * 512 + ((nc ^ (k_loc & 7)) * 16));
            }
        }
    }

    float acc[4][8][4];
    #pragma unroll
    for (int mt = 0; mt < 4; mt++)
        #pragma unroll
        for (int nt = 0; nt < 8; nt++)
            #pragma unroll
            for (int i = 0; i < 4; i++) acc[mt][nt][i] = 0.f;

    const int nk = K / TBK;

    #pragma unroll
    for (int c = 0; c < NS - 1; c++) {
        uint32_t base = uS + (c & 3) * ST_BYTES;
        const __half* Ap = Ag + (size_t)c * TBK;
        const __half* Bp = Bg + (size_t)c * TBK * N;
        CP16(base + stA[0], Ap);
        CP16(base + stA[1], Ap + 8);
        #pragma unroll
        for (int j = 0; j < 4; j++)
            CP16(base + A_ST + stB[j], Bp + 64 * j);
        CP_COMMIT();
    }

    for (int c = 0; c < nk; c++) {
        CP_WAIT2();
        __syncthreads();

        const uint32_t aoff = uS + (c & 3) * ST_BYTES;
        const uint32_t boff = aoff + A_ST;
        #pragma unroll
        for (int s = 0; s < 2; s++) {
            unsigned af[4][4];
            #pragma unroll
            for (int mt = 0; mt < 4; mt++)
                LDSM_X4(af[mt][0], af[mt][1], af[mt][2], af[mt][3],
                        aoff + ldA[s] + mt * 1024);
            unsigned bf[8][2];
            #pragma unroll
            for (int ng = 0; ng < 4; ng++) {
                unsigned r0, r1, r2, r3;
                LDSM_X4_T(r0, r1, r2, r3, boff + ldBt[s][ng]);
                bf[2 * ng + 0][0] = r0; bf[2 * ng + 0][1] = r2;
                bf[2 * ng + 1][0] = r1; bf[2 * ng + 1][1] = r3;
            }
            #pragma unroll
            for (int mt = 0; mt < 4; mt++)
                #pragma unroll
                for (int nt = 0; nt < 8; nt++)
                    mma_f16(acc[mt][nt], af[mt], bf[nt]);
        }

        const int cn = c + NS - 1;
        if (cn < nk) {
            uint32_t base = uS + (cn & 3) * ST_BYTES;
            const __half* Ap = Ag + (size_t)cn * TBK;
            const __half* Bp = Bg + (size_t)cn * TBK * N;
            CP16(base + stA[0], Ap);
            CP16(base + stA[1], Ap + 8);
            #pragma unroll
            for (int j = 0; j < 4; j++)
                CP16(base + A_ST + stB[j], Bp + 64 * j);
        }
        CP_COMMIT();
    }

    const int lr = lane >> 2, lc = lane & 3;
    #pragma unroll
    for (int mt = 0; mt < 4; mt++) {
        #pragma unroll
        for (int nt = 0; nt < 8; nt++) {
            int gr = rowBase + wm + mt * 16 + lr;
            int gc = colBase + wn + nt * 8 + 2 * lc;
            if (OUT_HALF) {
                __half* C = (__half*)Cv;
                *(unsigned*)&C[(size_t)gr * N + gc] =
                    pack2(acc[mt][nt][0], acc[mt][nt][1]);
                *(unsigned*)&C[(size_t)(gr + 8) * N + gc] =
                    pack2(acc[mt][nt][2], acc[mt][nt][3]);
            } else {
                float* C = (float*)Cv;
                *(float2*)&C[(size_t)gr * N + gc] =
                    make_float2(acc[mt][nt][0], acc[mt][nt][1]);
                *(float2*)&C[(size_t)(gr + 8) * N + gc] =
                    make_float2(acc[mt][nt][2], acc[mt][nt][3]);
            }
        }
    }
}

// ================= fused RoPE(Q,K) + V reshape =================
// qkv columns: [0:4096)=q, [4096:8192)=v, [8192:12288)=k
__global__ void ropev_kernel(
    const __half* __restrict__ qkv, const int* __restrict__ pos_ids,
    __half* __restrict__ Q, __half* __restrict__ K, __half* __restrict__ V)
{
    size_t p = (size_t)blockIdx.x * blockDim.x + threadIdx.x;
    int row = (int)(p / 6144);        // b*S + s
    int cp  = (int)(p % 6144);        // half2-pair index within row
    int sect = cp >> 11;              // 0=q, 1=v, 2=k
    int f = (cp & 2047) * 2;
    int col = sect * 4096 + f;
    int b = row >> 11, s = row & 2047;
    int hh = f >> 8, d = f & 255;

    __half2 h = *(const __half2*)&qkv[(size_t)row * F3H + col];
    size_t dst = ((size_t)((b * NHc + hh) * Sc + s)) * HDc + d;

    if (sect == 1) {
        *(__half2*)&V[dst] = h;
    } else {
        float2 x = __half22float2(h);
        float2 y = x;
        if (d < 64) {
            float inv = expf(-(float)d * (9.210340371976184f / 64.f));
            float fr = (float)pos_ids[row] * inv;
            float c, sn;
            sincosf(fr, &sn, &c);
            y.x = x.x * c - x.y * sn;
            y.y = x.y * c + x.x * sn;
        }
        __half2 o = __floats2half2_rn(y.x, y.y);
        if (sect == 2) *(__half2*)&K[dst] = o;
        else           *(__half2*)&Q[dst] = o;
    }
}

// ================= fp16 flash attention, 128-q tile, warp-local softmax =================
// smem: Q 64K | K[2] 64K | V[2] 64K | P 16K
#define A5Q 0
#define A5K 65536
#define A5V 131072
#define A5P 196608
#define ATT5_SMEM 212992

__global__ __launch_bounds__(256, 1) void attn5_kernel(
    const __half* __restrict__ Qh, const __half* __restrict__ Kh,
    const __half* __restrict__ Vh, __half* __restrict__ O)
{
    extern __shared__ char smc[];
    char* Ph = smc + A5P;
    const uint32_t uBase = smem_u32(smc);
    const uint32_t uQ = uBase + A5Q;
    const uint32_t uK = uBase + A5K;
    const uint32_t uV = uBase + A5V;
    const uint32_t uP = uBase + A5P;

    const int tid = threadIdx.x, lane = tid & 31, wid = tid >> 5;
    const int lr = lane >> 2, lc = lane & 3;
    const int wm = wid * 16;                    // warp owns rows wm..wm+15
    const int qt = (Sc / 128 - 1) - blockIdx.x; // heavy tiles first
    const int hh = blockIdx.y, b = blockIdx.z;
    const int q0 = qt * 128;
    const size_t bh = (size_t)(b * NHc + hh);

    const __half* Qg = Qh + bh * Sc * HDc;
    const __half* Kg = Kh + bh * Sc * HDc;
    const __half* Vg = Vh + bh * Sc * HDc;

    // staging geometry
    const int qrow = tid >> 1;                 // Q: 128 rows, 2 threads/row
    const int qc0  = (tid & 1) * 16;
    const int srow = tid >> 2;                 // K/V: 64 rows, 4 threads/row
    const int sc0  = (tid & 3) * 8;
    uint32_t stKV[8];
    #pragma unroll
    for (int j = 0; j < 8; j++) {
        int c = sc0 + j;
        stKV[j] = (uint32_t)(srow * 512 + ((c ^ (srow & 7)) * 16));
    }

    // prologue: Q + K/V tile 0 via cp.async
    #pragma unroll
    for (int j = 0; j < 16; j++) {
        int c = qc0 + j;
        CP16(uQ + qrow * 512 + ((c ^ (qrow & 7)) * 16),
             Qg + (size_t)(q0 + qrow) * HDc + c * 8);
    }
    {
        const __half* Kp = Kg + (size_t)srow * HDc + sc0 * 8;
        const __half* Vp = Vg + (size_t)srow * HDc + sc0 * 8;
        #pragma unroll
        for (int j = 0; j < 8; j++) {
            CP16(uK + stKV[j], Kp + j * 8);
            CP16(uV + stKV[j], Vp + j * 8);
        }
        CP_COMMIT();
    }

    // per-thread stats (rows wm+lr, wm+lr+8)
    float m0 = -1e30f, m1 = -1e30f, l0 = 0.f, l1 = 0.f;
    float o[32][4];
    #pragma unroll
    for (int nt = 0; nt < 32; nt++)
        #pragma unroll
        for (int i = 0; i < 4; i++) o[nt][i] = 0.f;

    const int rowa = (lane & 7) + ((lane >> 3) & 1) * 8;
    const int arow = wm + rowa;
    const uint32_t aQbase = uQ + arow * 512;
    const uint32_t aPbase = uP + arow * 128;
    const int a_sw = arow & 7;
    const int r0l = wm + lr, r1l = wm + lr + 8;
    const int ktmax = 2 * qt + 1;

    for (int kt = 0; kt <= ktmax; kt++) {
        const int buf = kt & 1;
        const uint32_t uKb = uK + buf * 32768;
        const uint32_t uVb = uV + buf * 32768;

        CP_WAIT0();
        __syncthreads();

        if (kt < ktmax) {
            const int kn = (kt + 1) * 64;
            const __half* Kp = Kg + (size_t)(kn + srow) * HDc + sc0 * 8;
            const __half* Vp = Vg + (size_t)(kn + srow) * HDc + sc0 * 8;
            const uint32_t uKn = uK + (buf ^ 1) * 32768;
            const uint32_t uVn = uV + (buf ^ 1) * 32768;
            #pragma unroll
            for (int j = 0; j < 8; j++) {
                CP16(uKn + stKV[j], Kp + j * 8);
                CP16(uVn + stKV[j], Vp + j * 8);
            }
        }
        CP_COMMIT();

        const int k0 = kt * 64;

        // ---- S = Q K^T (per warp: 16 x 64) ----
        float sacc[8][4];
        #pragma unroll
        for (int nt = 0; nt < 8; nt++)
            #pragma unroll
            for (int i = 0; i < 4; i++) sacc[nt][i] = 0.f;

        #pragma unroll
        for (int j = 0; j < 16; j++) {
            const int kc = 2 * j + (lane >> 4);
            unsigned a0, a1, a2, a3;
            LDSM_X4(a0, a1, a2, a3, aQbase + ((kc ^ a_sw) * 16));
            unsigned af[4] = {a0, a1, a2, a3};
            #pragma unroll
            for (int g = 0; g < 4; g++) {
                const int nrow = g * 16 + rowa;
                unsigned r0, r1, r2, r3;
                LDSM_X4(r0, r1, r2, r3, uKb + nrow * 512 + ((kc ^ (nrow & 7)) * 16));
                unsigned b0[2] = {r0, r2}, b1[2] = {r1, r3};
                mma_f16(sacc[2 * g + 0], af, b0);
                mma_f16(sacc[2 * g + 1], af, b1);
            }
        }

        // scale + causal mask
        {
            const bool diag = (kt >= 2 * qt);
            const int qg0 = q0 + r0l, qg1 = q0 + r1l;
            #pragma unroll
            for (int nt = 0; nt < 8; nt++) {
                const int cg = k0 + nt * 8 + 2 * lc;
                sacc[nt][0] *= 0.0625f; sacc[nt][1] *= 0.0625f;
                sacc[nt][2] *= 0.0625f; sacc[nt][3] *= 0.0625f;
                if (diag) {
                    if (cg     > qg0) sacc[nt][0] = -1e30f;
                    if (cg + 1 > qg0) sacc[nt][1] = -1e30f;
                    if (cg     > qg1) sacc[nt][2] = -1e30f;
                    if (cg + 1 > qg1) sacc[nt][3] = -1e30f;
                }
            }
        }

        // ---- warp-local softmax (rows fully inside warp) ----
        float mx0 = -1e30f, mx1 = -1e30f;
        #pragma unroll
        for (int nt = 0; nt < 8; nt++) {
            mx0 = fmaxf(mx0, fmaxf(sacc[nt][0], sacc[nt][1]));
            mx1 = fmaxf(mx1, fmaxf(sacc[nt][2], sacc[nt][3]));
        }
        mx0 = fmaxf(mx0, __shfl_xor_sync(0xffffffffu, mx0, 1));
        mx0 = fmaxf(mx0, __shfl_xor_sync(0xffffffffu, mx0, 2));
        mx1 = fmaxf(mx1, __shfl_xor_sync(0xffffffffu, mx1, 1));
        mx1 = fmaxf(mx1, __shfl_xor_sync(0xffffffffu, mx1, 2));

        const float mn0 = fmaxf(m0, mx0);
        const float mn1 = fmaxf(m1, mx1);
        const float al0 = __expf(m0 - mn0);
        const float al1 = __expf(m1 - mn1);

        float s0 = 0.f, s1 = 0.f;
        #pragma unroll
        for (int nt = 0; nt < 8; nt++) {
            float p00 = __expf(sacc[nt][0] - mn0);
            float p01 = __expf(sacc[nt][1] - mn0);
            float p10 = __expf(sacc[nt][2] - mn1);
            float p11 = __expf(sacc[nt][3] - mn1);
            s0 += p00 + p01; s1 += p10 + p11;
            const int col = nt * 8 + 2 * lc;
            const int cch = col >> 3;
            const int cin = (col & 7) * 2;
            *(unsigned*)(Ph + r0l * 128 + ((cch ^ (r0l & 7)) * 16) + cin) = pack2(p00, p01);
            *(unsigned*)(Ph + r1l * 128 + ((cch ^ (r1l & 7)) * 16) + cin) = pack2(p10, p11);
        }
        s0 += __shfl_xor_sync(0xffffffffu, s0, 1);
        s0 += __shfl_xor_sync(0xffffffffu, s0, 2);
        s1 += __shfl_xor_sync(0xffffffffu, s1, 1);
        s1 += __shfl_xor_sync(0xffffffffu, s1, 2);

        m0 = mn0; m1 = mn1;
        l0 = l0 * al0 + s0;
        l1 = l1 * al1 + s1;

        __syncwarp();   // P rows (warp-private) visible to ldmatrix

        // rescale O
        #pragma unroll
        for (int nt = 0; nt < 32; nt++) {
            o[nt][0] *= al0; o[nt][1] *= al0;
            o[nt][2] *= al1; o[nt][3] *= al1;
        }

        // ---- O += P V (per warp: 16 x 256) ----
        #pragma unroll
        for (int j = 0; j < 4; j++) {
            const int kc = 2 * j + (lane >> 4);
            unsigned a0, a1, a2, a3;
            LDSM_X4(a0, a1, a2, a3, aPbase + ((kc ^ a_sw) * 16));
            unsigned af[4] = {a0, a1, a2, a3};
            const int k_loc = 16 * j + (lane >> 4) * 8 + (lane & 7);
            #pragma unroll
            for (int ng = 0; ng < 16; ng++) {
                const int nc = 2 * ng + ((lane >> 3) & 1);
                unsigned r0, r1, r2, r3;
                LDSM_X4_T(r0, r1, r2, r3,
                          uVb + k_loc * 512 + ((nc ^ (k_loc & 7)) * 16));
                unsigned b0[2] = {r0, r2}, b1[2] = {r1, r3};
                mma_f16(o[2 * ng + 0], af, b0);
                mma_f16(o[2 * ng + 1], af, b1);
            }
        }
        __syncwarp();   // done reading P before next iteration overwrites
    }

    // epilogue
    {
        const float i0 = 1.f / l0;
        const float i1 = 1.f / l1;
        #pragma unroll
        for (int nt = 0; nt < 32; nt++) {
            const int col = hh * HDc + nt * 8 + 2 * lc;
            size_t base0 = ((size_t)(b * Sc + q0 + r0l)) * Hc + col;
            size_t base1 = ((size_t)(b * Sc + q0 + r1l)) * Hc + col;
            *(unsigned*)&O[base0] = pack2(o[nt][0] * i0, o[nt][1] * i0);
            *(unsigned*)&O[base1] = pack2(o[nt][2] * i1, o[nt][3] * i1);
        }
    }
}

// ================= launch =================
extern "C" void kernel_launch(void* const* d_in, const int* in_sizes, int n_in,
                              void* d_out, int out_size)
{
    const float* hidden = (const float*)d_in[0];
    const int*   pos    = (const int*)d_in[1];
    const float* w_qkv  = (const float*)d_in[2];
    const float* w_out  = (const float*)d_in[3];
    float* out = (float*)d_out;

    __half *hidh, *wqkvh, *wouth, *qkvh, *Qh, *Kh, *Vh, *attnh;
    cudaGetSymbolAddress((void**)&hidh,  g_hidh);
    cudaGetSymbolAddress((void**)&wqkvh, g_wqkvh);
    cudaGetSymbolAddress((void**)&wouth, g_wouth);
    cudaGetSymbolAddress((void**)&qkvh,  g_qkvh);
    cudaGetSymbolAddress((void**)&Qh,    g_Qh);
    cudaGetSymbolAddress((void**)&Kh,    g_Kh);
    cudaGetSymbolAddress((void**)&Vh,    g_Vh);
    cudaGetSymbolAddress((void**)&attnh, g_attnh);

    cudaFuncSetAttribute(f16_gemm_cp<0>,
                         cudaFuncAttributeMaxDynamicSharedMemorySize, GEMM_SMEM);
    cudaFuncSetAttribute(f16_gemm_cp<1>,
                         cudaFuncAttributeMaxDynamicSharedMemorySize, GEMM_SMEM);
    cudaFuncSetAttribute(attn5_kernel,
                         cudaFuncAttributeMaxDynamicSharedMemorySize, ATT5_SMEM);

    // 0) fp32 -> fp16 conversions
    f2h_kernel<<<8192, 256>>>(hidden, hidh, 2097152);
    f2h_kernel<<<24576, 256>>>(w_qkv, wqkvh, 6291456);
    f2h_kernel<<<8192, 256>>>(w_out, wouth, 2097152);

    // 1) qkv = hidden @ w_qkv  (fp16 out)
    f16_gemm_cp<1><<<(4096 / TBM) * (F3H / TBN), 256, GEMM_SMEM>>>(
        hidh, wqkvh, qkvh, F3H, 4096, F3H / TBN);

    // 2) fused RoPE + V reshape
    ropev_kernel<<<98304, 256>>>(qkvh, pos, Qh, Kh, Vh);

    // 3) fp16 flash attention (128-q tile) -> attnh
    attn5_kernel<<<dim3(Sc / 128, NHc, Bc), 256, ATT5_SMEM>>>(Qh, Kh, Vh, attnh);

    // 4) out = attn @ w_out  (fp32 out)
    f16_gemm_cp<0><<<(4096 / TBM) * (Hc / TBN), 256, GEMM_SMEM>>>(
        attnh, wouth, out, Hc, 4096, Hc / TBN);
}